// round 6
// baseline (speedup 1.0000x reference)
#include <cuda_runtime.h>
#include <math.h>
#include <stdint.h>

// Problem constants
#define BB 4
#define SS 2048
#define EE 1024
#define HH 16
#define DH 64
#define FFD 4096
#define MM (BB * SS)          // 8192 tokens
#define E3 (3 * EE)           // 3072

// ---------------------------------------------------------------------------
// Scratch buffers (device globals; allocation-free)
// ---------------------------------------------------------------------------
__device__ __align__(128) float g_xn[(size_t)MM * EE];
__device__ __align__(128) float g_qkv[(size_t)MM * E3];
__device__ __align__(128) float g_attn[(size_t)MM * EE];
__device__ __align__(128) float g_x2[(size_t)MM * EE];
__device__ __align__(128) float g_fc1[(size_t)MM * FFD];
// tf32-rounded weights: qkv(3M) | o(1M) | fc1(4M) | fc2(4M)
__device__ __align__(128) float g_wc[(size_t)12 * 1024 * 1024];

// ---------------------------------------------------------------------------
// Helpers
// ---------------------------------------------------------------------------
__device__ __forceinline__ float rtf32(float x) {
    uint32_t u;
    asm("cvt.rna.tf32.f32 %0, %1;" : "=r"(u) : "f"(x));
    return __uint_as_float(u);
}
__device__ __forceinline__ uint32_t smem_u32(const void* p) {
    uint32_t a;
    asm("{ .reg .u64 t; cvta.to.shared.u64 t, %1; cvt.u32.u64 %0, t; }"
        : "=r"(a) : "l"(p));
    return a;
}
__device__ __forceinline__ void cp16(uint32_t s, const void* g) {
    asm volatile("cp.async.cg.shared.global [%0], [%1], 16;" :: "r"(s), "l"(g));
}
#define CP_COMMIT asm volatile("cp.async.commit_group;" ::: "memory")
#define CP_WAIT2  asm volatile("cp.async.wait_group 2;" ::: "memory")
#define CP_WAIT1  asm volatile("cp.async.wait_group 1;" ::: "memory")

__device__ __forceinline__ void mma8(float c[4], const uint32_t a[4],
                                     uint32_t b0, uint32_t b1) {
    asm volatile(
        "mma.sync.aligned.m16n8k8.row.col.f32.tf32.tf32.f32 "
        "{%0,%1,%2,%3}, {%4,%5,%6,%7}, {%8,%9}, {%0,%1,%2,%3};"
        : "+f"(c[0]), "+f"(c[1]), "+f"(c[2]), "+f"(c[3])
        : "r"(a[0]), "r"(a[1]), "r"(a[2]), "r"(a[3]), "r"(b0), "r"(b1));
}
// ldmatrix x4: four 8x8xb16 matrices == four 8x4xtf32 fragments
#define LDSM4(r, addr) \
    asm volatile("ldmatrix.sync.aligned.m8n8.x4.shared.b16 {%0,%1,%2,%3}, [%4];" \
        : "=r"((r)[0]), "=r"((r)[1]), "=r"((r)[2]), "=r"((r)[3]) : "r"(addr))

// ---------------------------------------------------------------------------
// Weight round-to-tf32 pass
// ---------------------------------------------------------------------------
__global__ void __launch_bounds__(256) round_kernel(const float* __restrict__ in,
                                                    float* __restrict__ out, int n) {
    int i = (blockIdx.x * 256 + threadIdx.x) * 4;
    if (i < n) {
        float4 v = *(const float4*)(in + i);
        v.x = rtf32(v.x); v.y = rtf32(v.y); v.z = rtf32(v.z); v.w = rtf32(v.w);
        *(float4*)(out + i) = v;
    }
}

// ---------------------------------------------------------------------------
// TF32 mma.sync GEMM NT, 4-stage cp.async ring, single sync per K-iter.
//   EPI 0: + bias, round to tf32   EPI 1: + bias + residual
//   EPI 2: + bias, exact GELU, round to tf32
// CTA 128x256x32, 8 warps (2Mx4N), warp tile 64x64.
// ---------------------------------------------------------------------------
#define BM 128
#define BN 256
#define BKF 32
#define SROW 36                                  // padded smem row stride (floats)
#define STG_FLOATS ((BM + BN) * SROW)            // 13824 floats per stage
#define STGB (STG_FLOATS * 4)                    // 55296 bytes
#define NSTAGE 4
#define GEMM_SMEM (NSTAGE * STGB)                // 221184 bytes

template <int EPI>
__global__ void __launch_bounds__(256, 1) gemm_mma(
    const float* __restrict__ A, const float* __restrict__ W,
    const float* __restrict__ bias, const float* __restrict__ res,
    float* __restrict__ C, int M, int N, int K)
{
    extern __shared__ float sm[];
    const int tid = threadIdx.x;
    const int bm = blockIdx.y * BM;
    const int bn = blockIdx.x * BN;
    const uint32_t sbase = smem_u32(sm);

    const int w = tid >> 5, lane = tid & 31;
    const int t = lane & 3;
    const int g = lane >> 2;
    const int wm = (w & 1) * 64;       // 2 M warps
    const int wn = (w >> 1) * 64;      // 4 N warps

    // ldmatrix source offsets (bytes, within stage)
    const uint32_t aLd = ((wm + (lane & 15)) * SROW + ((lane >> 4) << 2)) * 4;
    const uint32_t bLd = ((wn + (lane & 7) + ((lane >> 4) << 3)) * SROW
                          + (((lane >> 3) & 1) << 2)) * 4;

    const float* Ag = A + (size_t)bm * K;
    const float* Wg = W + (size_t)bn * K;

    float acc[4][8][4];
    #pragma unroll
    for (int mi = 0; mi < 4; mi++)
        #pragma unroll
        for (int ni = 0; ni < 8; ni++)
            #pragma unroll
            for (int j = 0; j < 4; j++) acc[mi][ni][j] = 0.0f;

    auto load_tile = [&](int stg, int kt) {
        const uint32_t dA = sbase + stg * STGB;
        const uint32_t dB = dA + BM * SROW * 4;
        const int kofs = kt * BKF;
        #pragma unroll
        for (int i = 0; i < 4; i++) {          // A: 128 rows x 8 chunks
            int chunk = tid + i * 256;
            int r = chunk >> 3, c = chunk & 7;
            cp16(dA + (r * SROW + c * 4) * 4, Ag + (size_t)r * K + kofs + c * 4);
        }
        #pragma unroll
        for (int i = 0; i < 8; i++) {          // B: 256 rows x 8 chunks
            int chunk = tid + i * 256;
            int r = chunk >> 3, c = chunk & 7;
            cp16(dB + (r * SROW + c * 4) * 4, Wg + (size_t)r * K + kofs + c * 4);
        }
    };

    const int nk = K / BKF;
    // prologue: tiles 0..2
    load_tile(0, 0); CP_COMMIT;
    load_tile(1, 1); CP_COMMIT;
    load_tile(2, 2); CP_COMMIT;

    for (int kt = 0; kt < nk; kt++) {
        const int s = kt & 3;
        CP_WAIT2;               // tile kt complete (for this thread)
        __syncthreads();        // all threads' tile kt visible; prev reads done
        const int nxt = kt + 3;
        if (nxt < nk) load_tile(nxt & 3, nxt);
        CP_COMMIT;              // unconditional: keeps group accounting aligned

        const uint32_t aBase = sbase + s * STGB + aLd;
        const uint32_t bBase = sbase + s * STGB + BM * SROW * 4 + bLd;

        #pragma unroll
        for (int ks = 0; ks < 4; ks++) {
            const uint32_t ko = ks * 32;   // 8 floats
            uint32_t a[4][4], bq[4][4];
            #pragma unroll
            for (int mi = 0; mi < 4; mi++)
                LDSM4(a[mi], aBase + mi * 16 * SROW * 4 + ko);
            #pragma unroll
            for (int p = 0; p < 4; p++)
                LDSM4(bq[p], bBase + p * 16 * SROW * 4 + ko);
            #pragma unroll
            for (int mi = 0; mi < 4; mi++)
                #pragma unroll
                for (int p = 0; p < 4; p++) {
                    mma8(acc[mi][2 * p],     a[mi], bq[p][0], bq[p][1]);
                    mma8(acc[mi][2 * p + 1], a[mi], bq[p][2], bq[p][3]);
                }
        }
    }

    // epilogue
    float bb[8][2];
    #pragma unroll
    for (int ni = 0; ni < 8; ni++) {
        int col = bn + wn + ni * 8 + t * 2;
        bb[ni][0] = __ldg(bias + col);
        bb[ni][1] = __ldg(bias + col + 1);
    }
    #pragma unroll
    for (int mi = 0; mi < 4; mi++) {
        #pragma unroll
        for (int h = 0; h < 2; h++) {
            const int row = bm + wm + mi * 16 + g + h * 8;
            #pragma unroll
            for (int ni = 0; ni < 8; ni++) {
                const int col = bn + wn + ni * 8 + t * 2;
                float o0 = acc[mi][ni][h * 2 + 0] + bb[ni][0];
                float o1 = acc[mi][ni][h * 2 + 1] + bb[ni][1];
                if (EPI == 2) {
                    o0 = 0.5f * o0 * (1.0f + erff(o0 * 0.70710678118654752f));
                    o1 = 0.5f * o1 * (1.0f + erff(o1 * 0.70710678118654752f));
                }
                if (EPI == 0 || EPI == 2) { o0 = rtf32(o0); o1 = rtf32(o1); }
                if (EPI == 1) {
                    const float2 rv = *(const float2*)(res + (size_t)row * N + col);
                    o0 += rv.x; o1 += rv.y;
                }
                *(float2*)(C + (size_t)row * N + col) = make_float2(o0, o1);
            }
        }
    }
}

// ---------------------------------------------------------------------------
// LayerNorm: one block per token row of 1024; output rounded to tf32
// ---------------------------------------------------------------------------
__global__ void __launch_bounds__(256) ln_kernel(const float* __restrict__ x,
                                                 const float* __restrict__ g,
                                                 const float* __restrict__ b,
                                                 float* __restrict__ out) {
    int row = blockIdx.x;
    const float4* xr = (const float4*)(x + (size_t)row * EE);
    float4 v = xr[threadIdx.x];
    float s  = v.x + v.y + v.z + v.w;
    float sq = v.x * v.x + v.y * v.y + v.z * v.z + v.w * v.w;
    #pragma unroll
    for (int o = 16; o; o >>= 1) {
        s  += __shfl_xor_sync(0xffffffffu, s,  o);
        sq += __shfl_xor_sync(0xffffffffu, sq, o);
    }
    __shared__ float ss[8], ssq[8];
    int w = threadIdx.x >> 5, ln = threadIdx.x & 31;
    if (ln == 0) { ss[w] = s; ssq[w] = sq; }
    __syncthreads();
    if (w == 0) {
        s  = (ln < 8) ? ss[ln]  : 0.0f;
        sq = (ln < 8) ? ssq[ln] : 0.0f;
        #pragma unroll
        for (int o = 4; o; o >>= 1) {
            s  += __shfl_xor_sync(0xffffffffu, s,  o);
            sq += __shfl_xor_sync(0xffffffffu, sq, o);
        }
        if (ln == 0) { ss[0] = s; ssq[0] = sq; }
    }
    __syncthreads();
    float mean = ss[0] * (1.0f / EE);
    float var  = ssq[0] * (1.0f / EE) - mean * mean;
    float rstd = rsqrtf(var + 1e-5f);
    int c = threadIdx.x * 4;
    float4 gg = *(const float4*)(g + c);
    float4 bb = *(const float4*)(b + c);
    float4 o4;
    o4.x = rtf32((v.x - mean) * rstd * gg.x + bb.x);
    o4.y = rtf32((v.y - mean) * rstd * gg.y + bb.y);
    o4.z = rtf32((v.z - mean) * rstd * gg.z + bb.z);
    o4.w = rtf32((v.w - mean) * rstd * gg.w + bb.w);
    ((float4*)(out + (size_t)row * EE))[threadIdx.x] = o4;
}

// ---------------------------------------------------------------------------
// Tensor-core flash attention, custom mask (j > i) || (j % TD == TD-1).
// 128-query CTA tile, 64-kv chunks, 8 warps x 16 q-rows, mma.sync + ldmatrix.
// ---------------------------------------------------------------------------
#define AST 68
#define ATT_SMEM ((128 * AST + 64 * AST + 64 * AST + 128 * AST) * 4)

__global__ void __launch_bounds__(256, 2) attn_tc(const float* __restrict__ qkv,
                                                  const int* __restrict__ tdp,
                                                  float* __restrict__ out) {
    extern __shared__ float sm[];
    float* Qs = sm;                    // [128][AST]
    float* Ks = Qs + 128 * AST;        // [64][AST]
    float* Vs = Ks + 64 * AST;         // [64][AST]
    float* Ps = Vs + 64 * AST;         // [128][AST]

    const int qb = blockIdx.x, bh = blockIdx.y;
    const int b = bh >> 4, h = bh & 15;
    const int TD = tdp[0];
    const int tid = threadIdx.x, w = tid >> 5, lane = tid & 31;
    const int g = lane >> 2, t = lane & 3;

    const size_t base = (size_t)b * SS * E3 + (size_t)h * DH;

    // ldmatrix offsets (bytes)
    const uint32_t qLd = smem_u32(Qs) +
        ((w * 16 + (lane & 15)) * AST + ((lane >> 4) << 2)) * 4;
    const uint32_t kLd = smem_u32(Ks) +
        (((lane & 7) + ((lane >> 4) << 3)) * AST + (((lane >> 3) & 1) << 2)) * 4;
    const uint32_t pLd = smem_u32(Ps) +
        ((w * 16 + (lane & 15)) * AST + ((lane >> 4) << 2)) * 4;

    // load Q tile 128x64
    for (int i = tid; i < 128 * 16; i += 256) {
        int r = i >> 4, c = (i & 15) * 4;
        float4 v = *(const float4*)(qkv + base + (size_t)(qb * 128 + r) * E3 + c);
        float* d = Qs + r * AST + c;
        d[0] = v.x; d[1] = v.y; d[2] = v.z; d[3] = v.w;
    }

    float m0 = -1e30f, m1 = -1e30f, l0 = 0.0f, l1 = 0.0f;
    float o[8][4];
    #pragma unroll
    for (int ni = 0; ni < 8; ni++)
        #pragma unroll
        for (int j = 0; j < 4; j++) o[ni][j] = 0.0f;

    const int ig0 = qb * 128 + w * 16 + g;
    const int ig1 = ig0 + 8;
    const int nkt = 2 * qb + 2;

    for (int kb = 0; kb < nkt; kb++) {
        __syncthreads();
        for (int i = tid; i < 64 * 16; i += 256) {
            int r = i >> 4, c = (i & 15) * 4;
            size_t off = base + (size_t)(kb * 64 + r) * E3 + c;
            float4 kv4 = *(const float4*)(qkv + off + EE);
            float4 vv4 = *(const float4*)(qkv + off + 2 * EE);
            float* dk = Ks + r * AST + c;
            float* dv = Vs + r * AST + c;
            dk[0] = kv4.x; dk[1] = kv4.y; dk[2] = kv4.z; dk[3] = kv4.w;
            dv[0] = vv4.x; dv[1] = vv4.y; dv[2] = vv4.z; dv[3] = vv4.w;
        }
        __syncthreads();

        // --- scores = Q @ K^T (ldmatrix fragments) ---
        float s[8][4];
        #pragma unroll
        for (int ni = 0; ni < 8; ni++)
            #pragma unroll
            for (int j = 0; j < 4; j++) s[ni][j] = 0.0f;

        #pragma unroll
        for (int ks = 0; ks < 8; ks++) {
            const uint32_t ko = ks * 32;
            uint32_t aq[4];
            LDSM4(aq, qLd + ko);
            #pragma unroll
            for (int p = 0; p < 4; p++) {
                uint32_t bk[4];
                LDSM4(bk, kLd + p * 16 * AST * 4 + ko);
                mma8(s[2 * p],     aq, bk[0], bk[1]);
                mma8(s[2 * p + 1], aq, bk[2], bk[3]);
            }
        }

        // --- mask + scale + online softmax ---
        float rm0 = -1e30f, rm1 = -1e30f;
        #pragma unroll
        for (int ni = 0; ni < 8; ni++) {
            #pragma unroll
            for (int j = 0; j < 2; j++) {
                const int col = kb * 64 + ni * 8 + t * 2 + j;
                const bool dead = ((col % TD) == TD - 1);
                float v0 = (dead || col > ig0) ? -1e30f : s[ni][j] * 0.125f;
                float v1 = (dead || col > ig1) ? -1e30f : s[ni][2 + j] * 0.125f;
                s[ni][j] = v0; s[ni][2 + j] = v1;
                rm0 = fmaxf(rm0, v0); rm1 = fmaxf(rm1, v1);
            }
        }
        #pragma unroll
        for (int ofs = 1; ofs < 4; ofs <<= 1) {
            rm0 = fmaxf(rm0, __shfl_xor_sync(0xffffffffu, rm0, ofs));
            rm1 = fmaxf(rm1, __shfl_xor_sync(0xffffffffu, rm1, ofs));
        }
        const float nm0 = fmaxf(m0, rm0), nm1 = fmaxf(m1, rm1);
        const float a0 = __expf(m0 - nm0), a1 = __expf(m1 - nm1);
        m0 = nm0; m1 = nm1;

        float rs0 = 0.0f, rs1 = 0.0f;
        float* pR0 = Ps + (w * 16 + g) * AST;
        float* pR1 = pR0 + 8 * AST;
        #pragma unroll
        for (int ni = 0; ni < 8; ni++) {
            float p00 = __expf(s[ni][0] - m0), p01 = __expf(s[ni][1] - m0);
            float p10 = __expf(s[ni][2] - m1), p11 = __expf(s[ni][3] - m1);
            rs0 += p00 + p01; rs1 += p10 + p11;
            const int c = ni * 8 + t * 2;
            *(float2*)(pR0 + c) = make_float2(rtf32(p00), rtf32(p01));
            *(float2*)(pR1 + c) = make_float2(rtf32(p10), rtf32(p11));
        }
        #pragma unroll
        for (int ofs = 1; ofs < 4; ofs <<= 1) {
            rs0 += __shfl_xor_sync(0xffffffffu, rs0, ofs);
            rs1 += __shfl_xor_sync(0xffffffffu, rs1, ofs);
        }
        l0 = l0 * a0 + rs0;
        l1 = l1 * a1 + rs1;
        #pragma unroll
        for (int ni = 0; ni < 8; ni++) {
            o[ni][0] *= a0; o[ni][1] *= a0;
            o[ni][2] *= a1; o[ni][3] *= a1;
        }
        __syncwarp();

        // --- O += P @ V ---
        #pragma unroll
        for (int ks = 0; ks < 8; ks++) {
            const uint32_t ko = ks * 32;
            const int k0 = ks * 8;
            uint32_t a[4];
            LDSM4(a, pLd + ko);
            #pragma unroll
            for (int ni = 0; ni < 8; ni++) {
                uint32_t b0 = __float_as_uint(Vs[(k0 + t) * AST + ni * 8 + g]);
                uint32_t b1 = __float_as_uint(Vs[(k0 + t + 4) * AST + ni * 8 + g]);
                mma8(o[ni], a, b0, b1);
            }
        }
    }

    // epilogue (rounded: feeds O-projection mma)
    const float inv0 = 1.0f / l0, inv1 = 1.0f / l1;
    const size_t r0o = ((size_t)(b * SS + qb * 128 + w * 16 + g)) * EE + h * DH;
    const size_t r1o = r0o + 8 * EE;
    #pragma unroll
    for (int ni = 0; ni < 8; ni++) {
        const int c = ni * 8 + t * 2;
        *(float2*)(out + r0o + c) =
            make_float2(rtf32(o[ni][0] * inv0), rtf32(o[ni][1] * inv0));
        *(float2*)(out + r1o + c) =
            make_float2(rtf32(o[ni][2] * inv1), rtf32(o[ni][3] * inv1));
    }
}

// ---------------------------------------------------------------------------
// Launch
// ---------------------------------------------------------------------------
extern "C" void kernel_launch(void* const* d_in, const int* in_sizes, int n_in,
                              void* d_out, int out_size) {
    const float* x      = (const float*)d_in[0];
    const int*   td     = (const int*)d_in[1];
    const float* ln1_g  = (const float*)d_in[2];
    const float* ln1_b  = (const float*)d_in[3];
    const float* ln2_g  = (const float*)d_in[4];
    const float* ln2_b  = (const float*)d_in[5];
    const float* w_qkv  = (const float*)d_in[6];
    const float* b_qkv  = (const float*)d_in[7];
    const float* w_o    = (const float*)d_in[8];
    const float* b_o    = (const float*)d_in[9];
    const float* w_fc1  = (const float*)d_in[10];
    const float* b_fc1  = (const float*)d_in[11];
    const float* w_fc2  = (const float*)d_in[12];
    const float* b_fc2  = (const float*)d_in[13];
    float* out = (float*)d_out;

    float *xn, *qkvb, *attnb, *x2, *fc1b, *wc;
    cudaGetSymbolAddress((void**)&xn,    g_xn);
    cudaGetSymbolAddress((void**)&qkvb,  g_qkv);
    cudaGetSymbolAddress((void**)&attnb, g_attn);
    cudaGetSymbolAddress((void**)&x2,    g_x2);
    cudaGetSymbolAddress((void**)&fc1b,  g_fc1);
    cudaGetSymbolAddress((void**)&wc,    g_wc);

    float* wc_qkv = wc;
    float* wc_o   = wc + (size_t)3 * 1024 * 1024;
    float* wc_fc1 = wc + (size_t)4 * 1024 * 1024;
    float* wc_fc2 = wc + (size_t)8 * 1024 * 1024;

    cudaFuncSetAttribute(gemm_mma<0>, cudaFuncAttributeMaxDynamicSharedMemorySize, GEMM_SMEM);
    cudaFuncSetAttribute(gemm_mma<1>, cudaFuncAttributeMaxDynamicSharedMemorySize, GEMM_SMEM);
    cudaFuncSetAttribute(gemm_mma<2>, cudaFuncAttributeMaxDynamicSharedMemorySize, GEMM_SMEM);
    cudaFuncSetAttribute(attn_tc, cudaFuncAttributeMaxDynamicSharedMemorySize, ATT_SMEM);

    // 0. Round weights to tf32 once per call
    round_kernel<<<(E3 * EE / 4 + 255) / 256, 256>>>(w_qkv, wc_qkv, E3 * EE);
    round_kernel<<<(EE * EE / 4 + 255) / 256, 256>>>(w_o,   wc_o,   EE * EE);
    round_kernel<<<(FFD * EE / 4 + 255) / 256, 256>>>(w_fc1, wc_fc1, FFD * EE);
    round_kernel<<<(EE * FFD / 4 + 255) / 256, 256>>>(w_fc2, wc_fc2, EE * FFD);

    // 1. LN1 (tf32-rounded output)
    ln_kernel<<<MM, 256>>>(x, ln1_g, ln1_b, xn);
    // 2. QKV projection (tf32-rounded output)
    gemm_mma<0><<<dim3(E3 / BN, MM / BM), 256, GEMM_SMEM>>>(xn, wc_qkv, b_qkv, nullptr,
                                                            qkvb, MM, E3, EE);
    // 3. Tensor-core attention
    attn_tc<<<dim3(SS / 128, BB * HH), 256, ATT_SMEM>>>(qkvb, td, attnb);
    // 4. O projection + residual
    gemm_mma<1><<<dim3(EE / BN, MM / BM), 256, GEMM_SMEM>>>(attnb, wc_o, b_o, x,
                                                            x2, MM, EE, EE);
    // 5. LN2
    ln_kernel<<<MM, 256>>>(x2, ln2_g, ln2_b, xn);
    // 6. FC1 + GELU (tf32-rounded output)
    gemm_mma<2><<<dim3(FFD / BN, MM / BM), 256, GEMM_SMEM>>>(xn, wc_fc1, b_fc1, nullptr,
                                                             fc1b, MM, FFD, EE);
    // 7. FC2 + residual -> out
    gemm_mma<1><<<dim3(EE / BN, MM / BM), 256, GEMM_SMEM>>>(fc1b, wc_fc2, b_fc2, x2,
                                                            out, MM, EE, FFD);
}

// round 8
// speedup vs baseline: 1.6186x; 1.6186x over previous
#include <cuda_runtime.h>
#include <cuda_fp16.h>
#include <math.h>
#include <stdint.h>

// Problem constants
#define BB 4
#define SS 2048
#define EE 1024
#define HH 16
#define DH 64
#define FFD 4096
#define MM (BB * SS)          // 8192 tokens
#define E3 (3 * EE)           // 3072

// ---------------------------------------------------------------------------
// Scratch buffers (device globals; allocation-free)
// ---------------------------------------------------------------------------
__device__ __align__(128) __half g_xn[(size_t)MM * EE];     // LN out (fp16)
__device__ __align__(128) float  g_qkv[(size_t)MM * E3];    // QKV (fp32, tf32-rounded)
__device__ __align__(128) __half g_attn[(size_t)MM * EE];   // attention out (fp16)
__device__ __align__(128) float  g_x2[(size_t)MM * EE];     // residual (fp32)
__device__ __align__(128) __half g_fc1[(size_t)MM * FFD];   // gelu(fc1) (fp16)
// fp16 weights: qkv(3M) | o(1M) | fc1(4M) | fc2(4M)
__device__ __align__(128) __half g_wc[(size_t)12 * 1024 * 1024];

// ---------------------------------------------------------------------------
// Helpers
// ---------------------------------------------------------------------------
__device__ __forceinline__ float rtf32(float x) {
    uint32_t u;
    asm("cvt.rna.tf32.f32 %0, %1;" : "=r"(u) : "f"(x));
    return __uint_as_float(u);
}
__device__ __forceinline__ uint32_t smem_u32(const void* p) {
    uint32_t a;
    asm("{ .reg .u64 t; cvta.to.shared.u64 t, %1; cvt.u32.u64 %0, t; }"
        : "=r"(a) : "l"(p));
    return a;
}
__device__ __forceinline__ void cp16(uint32_t s, const void* g) {
    asm volatile("cp.async.cg.shared.global [%0], [%1], 16;" :: "r"(s), "l"(g));
}
#define CP_COMMIT asm volatile("cp.async.commit_group;" ::: "memory")
#define CP_WAIT1  asm volatile("cp.async.wait_group 1;" ::: "memory")

// fp16 mma m16n8k16, fp32 accumulate
__device__ __forceinline__ void mmah(float c[4], const uint32_t a[4],
                                     uint32_t b0, uint32_t b1) {
    asm volatile(
        "mma.sync.aligned.m16n8k16.row.col.f32.f16.f16.f32 "
        "{%0,%1,%2,%3}, {%4,%5,%6,%7}, {%8,%9}, {%0,%1,%2,%3};"
        : "+f"(c[0]), "+f"(c[1]), "+f"(c[2]), "+f"(c[3])
        : "r"(a[0]), "r"(a[1]), "r"(a[2]), "r"(a[3]), "r"(b0), "r"(b1));
}
// tf32 mma m16n8k8 (attention, proven)
__device__ __forceinline__ void mma8(float c[4], const uint32_t a[4],
                                     uint32_t b0, uint32_t b1) {
    asm volatile(
        "mma.sync.aligned.m16n8k8.row.col.f32.tf32.tf32.f32 "
        "{%0,%1,%2,%3}, {%4,%5,%6,%7}, {%8,%9}, {%0,%1,%2,%3};"
        : "+f"(c[0]), "+f"(c[1]), "+f"(c[2]), "+f"(c[3])
        : "r"(a[0]), "r"(a[1]), "r"(a[2]), "r"(a[3]), "r"(b0), "r"(b1));
}
#define LDSM4(r, addr) \
    asm volatile("ldmatrix.sync.aligned.m8n8.x4.shared.b16 {%0,%1,%2,%3}, [%4];" \
        : "=r"((r)[0]), "=r"((r)[1]), "=r"((r)[2]), "=r"((r)[3]) : "r"(addr))

// ---------------------------------------------------------------------------
// Weight convert fp32 -> fp16
// ---------------------------------------------------------------------------
__global__ void __launch_bounds__(256) cvt_kernel(const float* __restrict__ in,
                                                  __half* __restrict__ out, int n) {
    int i = (blockIdx.x * 256 + threadIdx.x) * 8;
    if (i < n) {
        float4 v0 = *(const float4*)(in + i);
        float4 v1 = *(const float4*)(in + i + 4);
        __half2 h[4];
        h[0] = __floats2half2_rn(v0.x, v0.y);
        h[1] = __floats2half2_rn(v0.z, v0.w);
        h[2] = __floats2half2_rn(v1.x, v1.y);
        h[3] = __floats2half2_rn(v1.z, v1.w);
        *(uint2*)(out + i)     = make_uint2(*(uint32_t*)&h[0], *(uint32_t*)&h[1]);
        *(uint2*)(out + i + 4) = make_uint2(*(uint32_t*)&h[2], *(uint32_t*)&h[3]);
    }
}

// ---------------------------------------------------------------------------
// FP16 mma.sync GEMM NT: C[m,n] = sum_k A[m,k]*W[n,k] (+epilogue)
//   EPI 0: + bias, rtf32 -> float (QKV, feeds tf32 attention)
//   EPI 1: + bias + residual -> float
//   EPI 2: + bias, exact GELU -> half
// CTA 128x128x64(halves), 8 warps (4Mx2N), warp 32x64,
// R5-proven 2-stage cp.async pipeline; byte-identical smem addressing to R5.
// ---------------------------------------------------------------------------
#define BM 128
#define BN 128
#define BK 64                          // K-tile in halves (128 bytes/row, as R5)
#define SROWB 144                      // padded row stride in BYTES (as R5)
#define ASTGB (BM * SROWB)             // 18432 B
#define STGB (2 * ASTGB)               // 36864 B per stage
#define GEMM_SMEM (2 * STGB)           // 73728 B (2 stages)

template <int EPI>
__global__ void __launch_bounds__(256, 2) gemm_mma(
    const __half* __restrict__ A, const __half* __restrict__ W,
    const float* __restrict__ bias, const float* __restrict__ res,
    void* __restrict__ Cv, int M, int N, int K)
{
    extern __shared__ char smemraw[];
    const int tid = threadIdx.x;
    const int bm = blockIdx.y * BM;
    const int bn = blockIdx.x * BN;
    const uint32_t sbase = smem_u32(smemraw);

    const int w = tid >> 5, lane = tid & 31;
    const int t = lane & 3;
    const int g = lane >> 2;
    const int wm = (w & 3) * 32;       // 4 M warps
    const int wn = (w >> 2) * 64;      // 2 N warps

    // ldmatrix source offsets (bytes, within stage) — byte-identical to R5
    const uint32_t aLd = (wm + (lane & 15)) * SROWB + ((lane >> 4) << 4);
    const uint32_t bLd = (wn + (lane & 7) + ((lane >> 4) << 3)) * SROWB
                         + (((lane >> 3) & 1) << 4);

    const __half* Ag = A + (size_t)bm * K;
    const __half* Wg = W + (size_t)bn * K;

    float acc[2][8][4];
    #pragma unroll
    for (int mi = 0; mi < 2; mi++)
        #pragma unroll
        for (int ni = 0; ni < 8; ni++)
            #pragma unroll
            for (int j = 0; j < 4; j++) acc[mi][ni][j] = 0.0f;

    auto load_tile = [&](int stg, int kt) {
        const uint32_t dA = sbase + stg * STGB;
        const uint32_t dB = dA + ASTGB;
        const int kofs = kt * BK;
        #pragma unroll
        for (int i = 0; i < 4; i++) {       // A: 128 rows x 8 chunks (16B)
            int chunk = tid + i * 256;
            int r = chunk >> 3, c = chunk & 7;
            cp16(dA + r * SROWB + c * 16, Ag + (size_t)r * K + kofs + c * 8);
        }
        #pragma unroll
        for (int i = 0; i < 4; i++) {       // B: 128 rows x 8 chunks
            int chunk = tid + i * 256;
            int r = chunk >> 3, c = chunk & 7;
            cp16(dB + r * SROWB + c * 16, Wg + (size_t)r * K + kofs + c * 8);
        }
    };

    const int nk = K / BK;
    load_tile(0, 0);
    CP_COMMIT;

    for (int kt = 0; kt < nk; kt++) {
        const int buf = kt & 1;
        if (kt + 1 < nk) load_tile(buf ^ 1, kt + 1);
        CP_COMMIT;
        CP_WAIT1;
        __syncthreads();

        const uint32_t aBase = sbase + buf * STGB + aLd;
        const uint32_t bBase = sbase + buf * STGB + ASTGB + bLd;

        #pragma unroll
        for (int ks = 0; ks < 4; ks++) {  // 4 x k16 (32B per step, as R5)
            const uint32_t ko = ks * 32;
            uint32_t a0[4], a1[4], bq[4][4];
            LDSM4(a0, aBase + ko);
            LDSM4(a1, aBase + 16 * SROWB + ko);
            #pragma unroll
            for (int p = 0; p < 4; p++)
                LDSM4(bq[p], bBase + p * 16 * SROWB + ko);
            #pragma unroll
            for (int p = 0; p < 4; p++) {
                mmah(acc[0][2 * p],     a0, bq[p][0], bq[p][1]);
                mmah(acc[0][2 * p + 1], a0, bq[p][2], bq[p][3]);
                mmah(acc[1][2 * p],     a1, bq[p][0], bq[p][1]);
                mmah(acc[1][2 * p + 1], a1, bq[p][2], bq[p][3]);
            }
        }
        __syncthreads();
    }

    // epilogue
    float bb[8][2];
    #pragma unroll
    for (int ni = 0; ni < 8; ni++) {
        int col = bn + wn + ni * 8 + t * 2;
        bb[ni][0] = __ldg(bias + col);
        bb[ni][1] = __ldg(bias + col + 1);
    }
    #pragma unroll
    for (int mi = 0; mi < 2; mi++) {
        #pragma unroll
        for (int h = 0; h < 2; h++) {
            const int row = bm + wm + mi * 16 + g + h * 8;
            #pragma unroll
            for (int ni = 0; ni < 8; ni++) {
                const int col = bn + wn + ni * 8 + t * 2;
                float o0 = acc[mi][ni][h * 2 + 0] + bb[ni][0];
                float o1 = acc[mi][ni][h * 2 + 1] + bb[ni][1];
                if (EPI == 0) {
                    *(float2*)((float*)Cv + (size_t)row * N + col) =
                        make_float2(rtf32(o0), rtf32(o1));
                } else if (EPI == 1) {
                    const float2 rv = *(const float2*)(res + (size_t)row * N + col);
                    *(float2*)((float*)Cv + (size_t)row * N + col) =
                        make_float2(o0 + rv.x, o1 + rv.y);
                } else {
                    o0 = 0.5f * o0 * (1.0f + erff(o0 * 0.70710678118654752f));
                    o1 = 0.5f * o1 * (1.0f + erff(o1 * 0.70710678118654752f));
                    *(__half2*)((__half*)Cv + (size_t)row * N + col) =
                        __floats2half2_rn(o0, o1);
                }
            }
        }
    }
}

// ---------------------------------------------------------------------------
// LayerNorm: one block per token row of 1024; fp16 output (feeds GEMM A)
// ---------------------------------------------------------------------------
__global__ void __launch_bounds__(256) ln_kernel(const float* __restrict__ x,
                                                 const float* __restrict__ g,
                                                 const float* __restrict__ b,
                                                 __half* __restrict__ out) {
    int row = blockIdx.x;
    const float4* xr = (const float4*)(x + (size_t)row * EE);
    float4 v = xr[threadIdx.x];
    float s  = v.x + v.y + v.z + v.w;
    float sq = v.x * v.x + v.y * v.y + v.z * v.z + v.w * v.w;
    #pragma unroll
    for (int o = 16; o; o >>= 1) {
        s  += __shfl_xor_sync(0xffffffffu, s,  o);
        sq += __shfl_xor_sync(0xffffffffu, sq, o);
    }
    __shared__ float ss[8], ssq[8];
    int w = threadIdx.x >> 5, ln = threadIdx.x & 31;
    if (ln == 0) { ss[w] = s; ssq[w] = sq; }
    __syncthreads();
    if (w == 0) {
        s  = (ln < 8) ? ss[ln]  : 0.0f;
        sq = (ln < 8) ? ssq[ln] : 0.0f;
        #pragma unroll
        for (int o = 4; o; o >>= 1) {
            s  += __shfl_xor_sync(0xffffffffu, s,  o);
            sq += __shfl_xor_sync(0xffffffffu, sq, o);
        }
        if (ln == 0) { ss[0] = s; ssq[0] = sq; }
    }
    __syncthreads();
    float mean = ss[0] * (1.0f / EE);
    float var  = ssq[0] * (1.0f / EE) - mean * mean;
    float rstd = rsqrtf(var + 1e-5f);
    int c = threadIdx.x * 4;
    float4 gg = *(const float4*)(g + c);
    float4 bb = *(const float4*)(b + c);
    __half2 h0 = __floats2half2_rn((v.x - mean) * rstd * gg.x + bb.x,
                                   (v.y - mean) * rstd * gg.y + bb.y);
    __half2 h1 = __floats2half2_rn((v.z - mean) * rstd * gg.z + bb.z,
                                   (v.w - mean) * rstd * gg.w + bb.w);
    *(uint2*)(out + (size_t)row * EE + c) =
        make_uint2(*(uint32_t*)&h0, *(uint32_t*)&h1);
}

// ---------------------------------------------------------------------------
// TF32 tensor-core flash attention (R5-proven), mask (j>i)||(j%TD==TD-1).
// 128-query CTA tile, 64-kv chunks, 8 warps x 16 q-rows, mma.sync + ldmatrix.
// Input: fp32 tf32-rounded QKV. Output: fp16 (feeds O-projection GEMM).
// ---------------------------------------------------------------------------
#define AST 68
#define ATT_SMEM ((128 * AST + 64 * AST + 64 * AST + 128 * AST) * 4)

__global__ void __launch_bounds__(256, 2) attn_tc(const float* __restrict__ qkv,
                                                  const int* __restrict__ tdp,
                                                  __half* __restrict__ out) {
    extern __shared__ float sm[];
    float* Qs = sm;                    // [128][AST]
    float* Ks = Qs + 128 * AST;        // [64][AST]
    float* Vs = Ks + 64 * AST;         // [64][AST]
    float* Ps = Vs + 64 * AST;         // [128][AST]

    const int qb = blockIdx.x, bh = blockIdx.y;
    const int b = bh >> 4, h = bh & 15;
    const int TD = tdp[0];
    const int tid = threadIdx.x, w = tid >> 5, lane = tid & 31;
    const int g = lane >> 2, t = lane & 3;

    const size_t base = (size_t)b * SS * E3 + (size_t)h * DH;

    const uint32_t qLd = smem_u32(Qs) +
        ((w * 16 + (lane & 15)) * AST + ((lane >> 4) << 2)) * 4;
    const uint32_t kLd = smem_u32(Ks) +
        (((lane & 7) + ((lane >> 4) << 3)) * AST + (((lane >> 3) & 1) << 2)) * 4;
    const uint32_t pLd = smem_u32(Ps) +
        ((w * 16 + (lane & 15)) * AST + ((lane >> 4) << 2)) * 4;

    for (int i = tid; i < 128 * 16; i += 256) {
        int r = i >> 4, c = (i & 15) * 4;
        float4 v = *(const float4*)(qkv + base + (size_t)(qb * 128 + r) * E3 + c);
        float* d = Qs + r * AST + c;
        d[0] = v.x; d[1] = v.y; d[2] = v.z; d[3] = v.w;
    }

    float m0 = -1e30f, m1 = -1e30f, l0 = 0.0f, l1 = 0.0f;
    float o[8][4];
    #pragma unroll
    for (int ni = 0; ni < 8; ni++)
        #pragma unroll
        for (int j = 0; j < 4; j++) o[ni][j] = 0.0f;

    const int ig0 = qb * 128 + w * 16 + g;
    const int ig1 = ig0 + 8;
    const int nkt = 2 * qb + 2;

    for (int kb = 0; kb < nkt; kb++) {
        __syncthreads();
        for (int i = tid; i < 64 * 16; i += 256) {
            int r = i >> 4, c = (i & 15) * 4;
            size_t off = base + (size_t)(kb * 64 + r) * E3 + c;
            float4 kv4 = *(const float4*)(qkv + off + EE);
            float4 vv4 = *(const float4*)(qkv + off + 2 * EE);
            float* dk = Ks + r * AST + c;
            float* dv = Vs + r * AST + c;
            dk[0] = kv4.x; dk[1] = kv4.y; dk[2] = kv4.z; dk[3] = kv4.w;
            dv[0] = vv4.x; dv[1] = vv4.y; dv[2] = vv4.z; dv[3] = vv4.w;
        }
        __syncthreads();

        float s[8][4];
        #pragma unroll
        for (int ni = 0; ni < 8; ni++)
            #pragma unroll
            for (int j = 0; j < 4; j++) s[ni][j] = 0.0f;

        #pragma unroll
        for (int ks = 0; ks < 8; ks++) {
            const uint32_t ko = ks * 32;
            uint32_t aq[4];
            LDSM4(aq, qLd + ko);
            #pragma unroll
            for (int p = 0; p < 4; p++) {
                uint32_t bk[4];
                LDSM4(bk, kLd + p * 16 * AST * 4 + ko);
                mma8(s[2 * p],     aq, bk[0], bk[1]);
                mma8(s[2 * p + 1], aq, bk[2], bk[3]);
            }
        }

        float rm0 = -1e30f, rm1 = -1e30f;
        #pragma unroll
        for (int ni = 0; ni < 8; ni++) {
            #pragma unroll
            for (int j = 0; j < 2; j++) {
                const int col = kb * 64 + ni * 8 + t * 2 + j;
                const bool dead = ((col % TD) == TD - 1);
                float v0 = (dead || col > ig0) ? -1e30f : s[ni][j] * 0.125f;
                float v1 = (dead || col > ig1) ? -1e30f : s[ni][2 + j] * 0.125f;
                s[ni][j] = v0; s[ni][2 + j] = v1;
                rm0 = fmaxf(rm0, v0); rm1 = fmaxf(rm1, v1);
            }
        }
        #pragma unroll
        for (int ofs = 1; ofs < 4; ofs <<= 1) {
            rm0 = fmaxf(rm0, __shfl_xor_sync(0xffffffffu, rm0, ofs));
            rm1 = fmaxf(rm1, __shfl_xor_sync(0xffffffffu, rm1, ofs));
        }
        const float nm0 = fmaxf(m0, rm0), nm1 = fmaxf(m1, rm1);
        const float a0 = __expf(m0 - nm0), a1 = __expf(m1 - nm1);
        m0 = nm0; m1 = nm1;

        float rs0 = 0.0f, rs1 = 0.0f;
        float* pR0 = Ps + (w * 16 + g) * AST;
        float* pR1 = pR0 + 8 * AST;
        #pragma unroll
        for (int ni = 0; ni < 8; ni++) {
            float p00 = __expf(s[ni][0] - m0), p01 = __expf(s[ni][1] - m0);
            float p10 = __expf(s[ni][2] - m1), p11 = __expf(s[ni][3] - m1);
            rs0 += p00 + p01; rs1 += p10 + p11;
            const int c = ni * 8 + t * 2;
            *(float2*)(pR0 + c) = make_float2(rtf32(p00), rtf32(p01));
            *(float2*)(pR1 + c) = make_float2(rtf32(p10), rtf32(p11));
        }
        #pragma unroll
        for (int ofs = 1; ofs < 4; ofs <<= 1) {
            rs0 += __shfl_xor_sync(0xffffffffu, rs0, ofs);
            rs1 += __shfl_xor_sync(0xffffffffu, rs1, ofs);
        }
        l0 = l0 * a0 + rs0;
        l1 = l1 * a1 + rs1;
        #pragma unroll
        for (int ni = 0; ni < 8; ni++) {
            o[ni][0] *= a0; o[ni][1] *= a0;
            o[ni][2] *= a1; o[ni][3] *= a1;
        }
        __syncwarp();

        #pragma unroll
        for (int ks = 0; ks < 8; ks++) {
            const uint32_t ko = ks * 32;
            const int k0 = ks * 8;
            uint32_t a[4];
            LDSM4(a, pLd + ko);
            #pragma unroll
            for (int ni = 0; ni < 8; ni++) {
                uint32_t b0 = __float_as_uint(Vs[(k0 + t) * AST + ni * 8 + g]);
                uint32_t b1 = __float_as_uint(Vs[(k0 + t + 4) * AST + ni * 8 + g]);
                mma8(o[ni], a, b0, b1);
            }
        }
    }

    // epilogue -> fp16 (feeds O-projection fp16 GEMM)
    const float inv0 = 1.0f / l0, inv1 = 1.0f / l1;
    const size_t r0o = ((size_t)(b * SS + qb * 128 + w * 16 + g)) * EE + h * DH;
    const size_t r1o = r0o + 8 * EE;
    #pragma unroll
    for (int ni = 0; ni < 8; ni++) {
        const int c = ni * 8 + t * 2;
        *(__half2*)(out + r0o + c) = __floats2half2_rn(o[ni][0] * inv0, o[ni][1] * inv0);
        *(__half2*)(out + r1o + c) = __floats2half2_rn(o[ni][2] * inv1, o[ni][3] * inv1);
    }
}

// ---------------------------------------------------------------------------
// Launch
// ---------------------------------------------------------------------------
extern "C" void kernel_launch(void* const* d_in, const int* in_sizes, int n_in,
                              void* d_out, int out_size) {
    const float* x      = (const float*)d_in[0];
    const int*   td     = (const int*)d_in[1];
    const float* ln1_g  = (const float*)d_in[2];
    const float* ln1_b  = (const float*)d_in[3];
    const float* ln2_g  = (const float*)d_in[4];
    const float* ln2_b  = (const float*)d_in[5];
    const float* w_qkv  = (const float*)d_in[6];
    const float* b_qkv  = (const float*)d_in[7];
    const float* w_o    = (const float*)d_in[8];
    const float* b_o    = (const float*)d_in[9];
    const float* w_fc1  = (const float*)d_in[10];
    const float* b_fc1  = (const float*)d_in[11];
    const float* w_fc2  = (const float*)d_in[12];
    const float* b_fc2  = (const float*)d_in[13];
    float* out = (float*)d_out;

    __half *xn, *attnb, *fc1b, *wc;
    float *qkvb, *x2;
    cudaGetSymbolAddress((void**)&xn,    g_xn);
    cudaGetSymbolAddress((void**)&qkvb,  g_qkv);
    cudaGetSymbolAddress((void**)&attnb, g_attn);
    cudaGetSymbolAddress((void**)&x2,    g_x2);
    cudaGetSymbolAddress((void**)&fc1b,  g_fc1);
    cudaGetSymbolAddress((void**)&wc,    g_wc);

    __half* wc_qkv = wc;
    __half* wc_o   = wc + (size_t)3 * 1024 * 1024;
    __half* wc_fc1 = wc + (size_t)4 * 1024 * 1024;
    __half* wc_fc2 = wc + (size_t)8 * 1024 * 1024;

    cudaFuncSetAttribute(gemm_mma<0>, cudaFuncAttributeMaxDynamicSharedMemorySize, GEMM_SMEM);
    cudaFuncSetAttribute(gemm_mma<1>, cudaFuncAttributeMaxDynamicSharedMemorySize, GEMM_SMEM);
    cudaFuncSetAttribute(gemm_mma<2>, cudaFuncAttributeMaxDynamicSharedMemorySize, GEMM_SMEM);
    cudaFuncSetAttribute(attn_tc, cudaFuncAttributeMaxDynamicSharedMemorySize, ATT_SMEM);

    // 0. Convert weights to fp16 once per call
    cvt_kernel<<<(E3 * EE / 8 + 255) / 256, 256>>>(w_qkv, wc_qkv, E3 * EE);
    cvt_kernel<<<(EE * EE / 8 + 255) / 256, 256>>>(w_o,   wc_o,   EE * EE);
    cvt_kernel<<<(FFD * EE / 8 + 255) / 256, 256>>>(w_fc1, wc_fc1, FFD * EE);
    cvt_kernel<<<(EE * FFD / 8 + 255) / 256, 256>>>(w_fc2, wc_fc2, EE * FFD);

    // 1. LN1 -> fp16
    ln_kernel<<<MM, 256>>>(x, ln1_g, ln1_b, xn);
    // 2. QKV projection (fp16 in, fp32 tf32-rounded out)
    gemm_mma<0><<<dim3(E3 / BN, MM / BM), 256, GEMM_SMEM>>>(xn, wc_qkv, b_qkv, nullptr,
                                                            qkvb, MM, E3, EE);
    // 3. TF32 tensor-core attention (proven) -> fp16
    attn_tc<<<dim3(SS / 128, BB * HH), 256, ATT_SMEM>>>(qkvb, td, attnb);
    // 4. O projection + residual -> fp32
    gemm_mma<1><<<dim3(EE / BN, MM / BM), 256, GEMM_SMEM>>>(attnb, wc_o, b_o, x,
                                                            x2, MM, EE, EE);
    // 5. LN2 -> fp16
    ln_kernel<<<MM, 256>>>(x2, ln2_g, ln2_b, xn);
    // 6. FC1 + GELU -> fp16
    gemm_mma<2><<<dim3(FFD / BN, MM / BM), 256, GEMM_SMEM>>>(xn, wc_fc1, b_fc1, nullptr,
                                                             fc1b, MM, FFD, EE);
    // 7. FC2 + residual -> fp32 out
    gemm_mma<1><<<dim3(EE / BN, MM / BM), 256, GEMM_SMEM>>>(fc1b, wc_fc2, b_fc2, x2,
                                                            out, MM, EE, FFD);
}

// round 10
// speedup vs baseline: 1.9398x; 1.1984x over previous
#include <cuda_runtime.h>
#include <cuda_fp16.h>
#include <math.h>
#include <stdint.h>

// Problem constants
#define BB 4
#define SS 2048
#define EE 1024
#define HH 16
#define DH 64
#define FFD 4096
#define MM (BB * SS)          // 8192 tokens
#define E3 (3 * EE)           // 3072

// ---------------------------------------------------------------------------
// Scratch buffers (device globals; allocation-free)
// ---------------------------------------------------------------------------
__device__ __align__(128) __half g_xn[(size_t)MM * EE];     // LN out (fp16)
__device__ __align__(128) __half g_qkv[(size_t)MM * E3];    // QKV (fp16)
__device__ __align__(128) __half g_attn[(size_t)MM * EE];   // attention out (fp16)
__device__ __align__(128) float  g_x2[(size_t)MM * EE];     // residual (fp32)
__device__ __align__(128) __half g_fc1[(size_t)MM * FFD];   // gelu(fc1) (fp16)
// fp16 weights: qkv(3M) | o(1M) | fc1(4M) | fc2(4M)
__device__ __align__(128) __half g_wc[(size_t)12 * 1024 * 1024];

// ---------------------------------------------------------------------------
// Helpers
// ---------------------------------------------------------------------------
__device__ __forceinline__ uint32_t smem_u32(const void* p) {
    uint32_t a;
    asm("{ .reg .u64 t; cvta.to.shared.u64 t, %1; cvt.u32.u64 %0, t; }"
        : "=r"(a) : "l"(p));
    return a;
}
__device__ __forceinline__ void cp16(uint32_t s, const void* g) {
    asm volatile("cp.async.cg.shared.global [%0], [%1], 16;" :: "r"(s), "l"(g));
}
#define CP_COMMIT asm volatile("cp.async.commit_group;" ::: "memory")
#define CP_WAIT1  asm volatile("cp.async.wait_group 1;" ::: "memory")

// fp16 mma m16n8k16, fp32 accumulate
__device__ __forceinline__ void mmah(float c[4], const uint32_t a[4],
                                     uint32_t b0, uint32_t b1) {
    asm volatile(
        "mma.sync.aligned.m16n8k16.row.col.f32.f16.f16.f32 "
        "{%0,%1,%2,%3}, {%4,%5,%6,%7}, {%8,%9}, {%0,%1,%2,%3};"
        : "+f"(c[0]), "+f"(c[1]), "+f"(c[2]), "+f"(c[3])
        : "r"(a[0]), "r"(a[1]), "r"(a[2]), "r"(a[3]), "r"(b0), "r"(b1));
}
#define LDSM4(r, addr) \
    asm volatile("ldmatrix.sync.aligned.m8n8.x4.shared.b16 {%0,%1,%2,%3}, [%4];" \
        : "=r"((r)[0]), "=r"((r)[1]), "=r"((r)[2]), "=r"((r)[3]) : "r"(addr))

__device__ __forceinline__ uint32_t packh2(__half lo, __half hi) {
    __half2 h = __halves2half2(lo, hi);
    return *(uint32_t*)&h;
}

// ---------------------------------------------------------------------------
// Weight convert fp32 -> fp16
// ---------------------------------------------------------------------------
__global__ void __launch_bounds__(256) cvt_kernel(const float* __restrict__ in,
                                                  __half* __restrict__ out, int n) {
    int i = (blockIdx.x * 256 + threadIdx.x) * 8;
    if (i < n) {
        float4 v0 = *(const float4*)(in + i);
        float4 v1 = *(const float4*)(in + i + 4);
        __half2 h[4];
        h[0] = __floats2half2_rn(v0.x, v0.y);
        h[1] = __floats2half2_rn(v0.z, v0.w);
        h[2] = __floats2half2_rn(v1.x, v1.y);
        h[3] = __floats2half2_rn(v1.z, v1.w);
        *(uint2*)(out + i)     = make_uint2(*(uint32_t*)&h[0], *(uint32_t*)&h[1]);
        *(uint2*)(out + i + 4) = make_uint2(*(uint32_t*)&h[2], *(uint32_t*)&h[3]);
    }
}

// ---------------------------------------------------------------------------
// FP16 mma.sync GEMM NT: C[m,n] = sum_k A[m,k]*W[n,k] (+epilogue)
//   EPI 0: + bias -> half (QKV)
//   EPI 1: + bias + residual -> float
//   EPI 2: + bias, exact GELU -> half
// CTA 128x128x64(halves), 8 warps (4Mx2N), warp 32x64, 2-stage cp.async.
// ---------------------------------------------------------------------------
#define BM 128
#define BN 128
#define BK 64                          // K-tile in halves
#define SROWB 144                      // padded row stride in BYTES
#define ASTGB (BM * SROWB)             // 18432 B
#define STGB (2 * ASTGB)               // 36864 B per stage
#define GEMM_SMEM (2 * STGB)           // 73728 B

template <int EPI>
__global__ void __launch_bounds__(256, 2) gemm_mma(
    const __half* __restrict__ A, const __half* __restrict__ W,
    const float* __restrict__ bias, const float* __restrict__ res,
    void* __restrict__ Cv, int M, int N, int K)
{
    extern __shared__ char smemraw[];
    const int tid = threadIdx.x;
    const int bm = blockIdx.y * BM;
    const int bn = blockIdx.x * BN;
    const uint32_t sbase = smem_u32(smemraw);

    const int w = tid >> 5, lane = tid & 31;
    const int t = lane & 3;
    const int g = lane >> 2;
    const int wm = (w & 3) * 32;       // 4 M warps
    const int wn = (w >> 2) * 64;      // 2 N warps

    const uint32_t aLd = (wm + (lane & 15)) * SROWB + ((lane >> 4) << 4);
    const uint32_t bLd = (wn + (lane & 7) + ((lane >> 4) << 3)) * SROWB
                         + (((lane >> 3) & 1) << 4);

    const __half* Ag = A + (size_t)bm * K;
    const __half* Wg = W + (size_t)bn * K;

    float acc[2][8][4];
    #pragma unroll
    for (int mi = 0; mi < 2; mi++)
        #pragma unroll
        for (int ni = 0; ni < 8; ni++)
            #pragma unroll
            for (int j = 0; j < 4; j++) acc[mi][ni][j] = 0.0f;

    auto load_tile = [&](int stg, int kt) {
        const uint32_t dA = sbase + stg * STGB;
        const uint32_t dB = dA + ASTGB;
        const int kofs = kt * BK;
        #pragma unroll
        for (int i = 0; i < 4; i++) {
            int chunk = tid + i * 256;
            int r = chunk >> 3, c = chunk & 7;
            cp16(dA + r * SROWB + c * 16, Ag + (size_t)r * K + kofs + c * 8);
        }
        #pragma unroll
        for (int i = 0; i < 4; i++) {
            int chunk = tid + i * 256;
            int r = chunk >> 3, c = chunk & 7;
            cp16(dB + r * SROWB + c * 16, Wg + (size_t)r * K + kofs + c * 8);
        }
    };

    const int nk = K / BK;
    load_tile(0, 0);
    CP_COMMIT;

    for (int kt = 0; kt < nk; kt++) {
        const int buf = kt & 1;
        if (kt + 1 < nk) load_tile(buf ^ 1, kt + 1);
        CP_COMMIT;
        CP_WAIT1;
        __syncthreads();

        const uint32_t aBase = sbase + buf * STGB + aLd;
        const uint32_t bBase = sbase + buf * STGB + ASTGB + bLd;

        #pragma unroll
        for (int ks = 0; ks < 4; ks++) {
            const uint32_t ko = ks * 32;
            uint32_t a0[4], a1[4], bq[4][4];
            LDSM4(a0, aBase + ko);
            LDSM4(a1, aBase + 16 * SROWB + ko);
            #pragma unroll
            for (int p = 0; p < 4; p++)
                LDSM4(bq[p], bBase + p * 16 * SROWB + ko);
            #pragma unroll
            for (int p = 0; p < 4; p++) {
                mmah(acc[0][2 * p],     a0, bq[p][0], bq[p][1]);
                mmah(acc[0][2 * p + 1], a0, bq[p][2], bq[p][3]);
                mmah(acc[1][2 * p],     a1, bq[p][0], bq[p][1]);
                mmah(acc[1][2 * p + 1], a1, bq[p][2], bq[p][3]);
            }
        }
        __syncthreads();
    }

    // epilogue
    float bb[8][2];
    #pragma unroll
    for (int ni = 0; ni < 8; ni++) {
        int col = bn + wn + ni * 8 + t * 2;
        bb[ni][0] = __ldg(bias + col);
        bb[ni][1] = __ldg(bias + col + 1);
    }
    #pragma unroll
    for (int mi = 0; mi < 2; mi++) {
        #pragma unroll
        for (int h = 0; h < 2; h++) {
            const int row = bm + wm + mi * 16 + g + h * 8;
            #pragma unroll
            for (int ni = 0; ni < 8; ni++) {
                const int col = bn + wn + ni * 8 + t * 2;
                float o0 = acc[mi][ni][h * 2 + 0] + bb[ni][0];
                float o1 = acc[mi][ni][h * 2 + 1] + bb[ni][1];
                if (EPI == 0) {
                    *(__half2*)((__half*)Cv + (size_t)row * N + col) =
                        __floats2half2_rn(o0, o1);
                } else if (EPI == 1) {
                    const float2 rv = *(const float2*)(res + (size_t)row * N + col);
                    *(float2*)((float*)Cv + (size_t)row * N + col) =
                        make_float2(o0 + rv.x, o1 + rv.y);
                } else {
                    o0 = 0.5f * o0 * (1.0f + erff(o0 * 0.70710678118654752f));
                    o1 = 0.5f * o1 * (1.0f + erff(o1 * 0.70710678118654752f));
                    *(__half2*)((__half*)Cv + (size_t)row * N + col) =
                        __floats2half2_rn(o0, o1);
                }
            }
        }
    }
}

// ---------------------------------------------------------------------------
// LayerNorm: one block per token row of 1024; fp16 output
// ---------------------------------------------------------------------------
__global__ void __launch_bounds__(256) ln_kernel(const float* __restrict__ x,
                                                 const float* __restrict__ g,
                                                 const float* __restrict__ b,
                                                 __half* __restrict__ out) {
    int row = blockIdx.x;
    const float4* xr = (const float4*)(x + (size_t)row * EE);
    float4 v = xr[threadIdx.x];
    float s  = v.x + v.y + v.z + v.w;
    float sq = v.x * v.x + v.y * v.y + v.z * v.z + v.w * v.w;
    #pragma unroll
    for (int o = 16; o; o >>= 1) {
        s  += __shfl_xor_sync(0xffffffffu, s,  o);
        sq += __shfl_xor_sync(0xffffffffu, sq, o);
    }
    __shared__ float ss[8], ssq[8];
    int w = threadIdx.x >> 5, ln = threadIdx.x & 31;
    if (ln == 0) { ss[w] = s; ssq[w] = sq; }
    __syncthreads();
    if (w == 0) {
        s  = (ln < 8) ? ss[ln]  : 0.0f;
        sq = (ln < 8) ? ssq[ln] : 0.0f;
        #pragma unroll
        for (int o = 4; o; o >>= 1) {
            s  += __shfl_xor_sync(0xffffffffu, s,  o);
            sq += __shfl_xor_sync(0xffffffffu, sq, o);
        }
        if (ln == 0) { ss[0] = s; ssq[0] = sq; }
    }
    __syncthreads();
    float mean = ss[0] * (1.0f / EE);
    float var  = ssq[0] * (1.0f / EE) - mean * mean;
    float rstd = rsqrtf(var + 1e-5f);
    int c = threadIdx.x * 4;
    float4 gg = *(const float4*)(g + c);
    float4 bb = *(const float4*)(b + c);
    __half2 h0 = __floats2half2_rn((v.x - mean) * rstd * gg.x + bb.x,
                                   (v.y - mean) * rstd * gg.y + bb.y);
    __half2 h1 = __floats2half2_rn((v.z - mean) * rstd * gg.z + bb.z,
                                   (v.w - mean) * rstd * gg.w + bb.w);
    *(uint2*)(out + (size_t)row * EE + c) =
        make_uint2(*(uint32_t*)&h0, *(uint32_t*)&h1);
}

// ---------------------------------------------------------------------------
// FP16 tensor-core flash attention, mask (j > i) || (j % TD == TD-1).
// 128-query CTA tile, 64-kv chunks, 8 warps x 16 q-rows, m16n8k16.
// QK via proven ldmatrix pattern; PV B-operand via scalar fragment packing.
// ---------------------------------------------------------------------------
#define AS2 72                          // smem row stride (halves) = 144 B
#define ATT_SMEM ((128 + 64 + 64 + 128) * AS2 * 2)

__global__ void __launch_bounds__(256, 2) attn_tc(const __half* __restrict__ qkv,
                                                  const int* __restrict__ tdp,
                                                  __half* __restrict__ out) {
    extern __shared__ char smemraw[];
    __half* Qs = (__half*)smemraw;     // [128][AS2]
    __half* Ks = Qs + 128 * AS2;       // [64][AS2]
    __half* Vs = Ks + 64 * AS2;        // [64][AS2]
    __half* Ps = Vs + 64 * AS2;        // [128][AS2]

    const int qb = blockIdx.x, bh = blockIdx.y;
    const int b = bh >> 4, h = bh & 15;
    const int TD = tdp[0];
    const int tid = threadIdx.x, w = tid >> 5, lane = tid & 31;
    const int g = lane >> 2, t = lane & 3;

    const size_t base = (size_t)b * SS * E3 + (size_t)h * DH;

    const uint32_t qLd = smem_u32(Qs) +
        (w * 16 + (lane & 15)) * (AS2 * 2) + ((lane >> 4) << 4);
    const uint32_t kLd = smem_u32(Ks) +
        ((lane & 7) + ((lane >> 4) << 3)) * (AS2 * 2) + (((lane >> 3) & 1) << 4);
    const uint32_t pLd = smem_u32(Ps) +
        (w * 16 + (lane & 15)) * (AS2 * 2) + ((lane >> 4) << 4);

    // load Q tile 128x64 halves (uint4 = 8 halves per chunk, 8 chunks/row)
    for (int i = tid; i < 128 * 8; i += 256) {
        int r = i >> 3, c = (i & 7) * 8;
        *(uint4*)(Qs + r * AS2 + c) =
            *(const uint4*)(qkv + base + (size_t)(qb * 128 + r) * E3 + c);
    }

    float m0 = -1e30f, m1 = -1e30f, l0 = 0.0f, l1 = 0.0f;
    float o[8][4];
    #pragma unroll
    for (int ni = 0; ni < 8; ni++)
        #pragma unroll
        for (int j = 0; j < 4; j++) o[ni][j] = 0.0f;

    const int ig0 = qb * 128 + w * 16 + g;
    const int ig1 = ig0 + 8;
    const int nkt = 2 * qb + 2;

    for (int kb = 0; kb < nkt; kb++) {
        __syncthreads();
        // K/V tiles: uint4 = 8 halves, stride 8 halves -> full coverage
        for (int i = tid; i < 64 * 8; i += 256) {
            int r = i >> 3, c = (i & 7) * 8;
            size_t off = base + (size_t)(kb * 64 + r) * E3 + c;
            *(uint4*)(Ks + r * AS2 + c) = *(const uint4*)(qkv + off + EE);
            *(uint4*)(Vs + r * AS2 + c) = *(const uint4*)(qkv + off + 2 * EE);
        }
        __syncthreads();

        // --- scores = Q @ K^T ---
        float s[8][4];
        #pragma unroll
        for (int ni = 0; ni < 8; ni++)
            #pragma unroll
            for (int j = 0; j < 4; j++) s[ni][j] = 0.0f;

        #pragma unroll
        for (int ks = 0; ks < 4; ks++) {
            const uint32_t ko = ks * 32;
            uint32_t aq[4];
            LDSM4(aq, qLd + ko);
            #pragma unroll
            for (int p = 0; p < 4; p++) {
                uint32_t bk[4];
                LDSM4(bk, kLd + p * 16 * (AS2 * 2) + ko);
                mmah(s[2 * p],     aq, bk[0], bk[1]);
                mmah(s[2 * p + 1], aq, bk[2], bk[3]);
            }
        }

        // --- mask + scale + online softmax ---
        float rm0 = -1e30f, rm1 = -1e30f;
        #pragma unroll
        for (int ni = 0; ni < 8; ni++) {
            #pragma unroll
            for (int j = 0; j < 2; j++) {
                const int col = kb * 64 + ni * 8 + t * 2 + j;
                const bool dead = ((col % TD) == TD - 1);
                float v0 = (dead || col > ig0) ? -1e30f : s[ni][j] * 0.125f;
                float v1 = (dead || col > ig1) ? -1e30f : s[ni][2 + j] * 0.125f;
                s[ni][j] = v0; s[ni][2 + j] = v1;
                rm0 = fmaxf(rm0, v0); rm1 = fmaxf(rm1, v1);
            }
        }
        #pragma unroll
        for (int ofs = 1; ofs < 4; ofs <<= 1) {
            rm0 = fmaxf(rm0, __shfl_xor_sync(0xffffffffu, rm0, ofs));
            rm1 = fmaxf(rm1, __shfl_xor_sync(0xffffffffu, rm1, ofs));
        }
        const float nm0 = fmaxf(m0, rm0), nm1 = fmaxf(m1, rm1);
        const float a0 = __expf(m0 - nm0), a1 = __expf(m1 - nm1);
        m0 = nm0; m1 = nm1;

        float rs0 = 0.0f, rs1 = 0.0f;
        __half* pR0 = Ps + (w * 16 + g) * AS2;
        __half* pR1 = pR0 + 8 * AS2;
        #pragma unroll
        for (int ni = 0; ni < 8; ni++) {
            float p00 = __expf(s[ni][0] - m0), p01 = __expf(s[ni][1] - m0);
            float p10 = __expf(s[ni][2] - m1), p11 = __expf(s[ni][3] - m1);
            rs0 += p00 + p01; rs1 += p10 + p11;
            const int c = ni * 8 + t * 2;
            *(__half2*)(pR0 + c) = __floats2half2_rn(p00, p01);
            *(__half2*)(pR1 + c) = __floats2half2_rn(p10, p11);
        }
        #pragma unroll
        for (int ofs = 1; ofs < 4; ofs <<= 1) {
            rs0 += __shfl_xor_sync(0xffffffffu, rs0, ofs);
            rs1 += __shfl_xor_sync(0xffffffffu, rs1, ofs);
        }
        l0 = l0 * a0 + rs0;
        l1 = l1 * a1 + rs1;
        #pragma unroll
        for (int ni = 0; ni < 8; ni++) {
            o[ni][0] *= a0; o[ni][1] *= a0;
            o[ni][2] *= a1; o[ni][3] *= a1;
        }
        __syncwarp();

        // --- O += P @ V (scalar B-fragment packing per PTX spec) ---
        #pragma unroll
        for (int ks = 0; ks < 4; ks++) {
            const uint32_t ko = ks * 32;
            const int k0 = ks * 16;
            uint32_t a[4];
            LDSM4(a, pLd + ko);
            const __half* v0r = Vs + (k0 + 2 * t) * AS2;      // k = 2t
            const __half* v1r = v0r + AS2;                    // k = 2t+1
            const __half* v2r = v0r + 8 * AS2;                // k = 2t+8
            const __half* v3r = v0r + 9 * AS2;                // k = 2t+9
            #pragma unroll
            for (int ni = 0; ni < 8; ni++) {
                const int c = ni * 8 + g;
                uint32_t b0 = packh2(v0r[c], v1r[c]);
                uint32_t b1 = packh2(v2r[c], v3r[c]);
                mmah(o[ni], a, b0, b1);
            }
        }
    }

    // epilogue -> fp16 (feeds O-projection fp16 GEMM)
    const float inv0 = 1.0f / l0, inv1 = 1.0f / l1;
    const size_t r0o = ((size_t)(b * SS + qb * 128 + w * 16 + g)) * EE + h * DH;
    const size_t r1o = r0o + 8 * EE;
    #pragma unroll
    for (int ni = 0; ni < 8; ni++) {
        const int c = ni * 8 + t * 2;
        *(__half2*)(out + r0o + c) = __floats2half2_rn(o[ni][0] * inv0, o[ni][1] * inv0);
        *(__half2*)(out + r1o + c) = __floats2half2_rn(o[ni][2] * inv1, o[ni][3] * inv1);
    }
}

// ---------------------------------------------------------------------------
// Launch
// ---------------------------------------------------------------------------
extern "C" void kernel_launch(void* const* d_in, const int* in_sizes, int n_in,
                              void* d_out, int out_size) {
    const float* x      = (const float*)d_in[0];
    const int*   td     = (const int*)d_in[1];
    const float* ln1_g  = (const float*)d_in[2];
    const float* ln1_b  = (const float*)d_in[3];
    const float* ln2_g  = (const float*)d_in[4];
    const float* ln2_b  = (const float*)d_in[5];
    const float* w_qkv  = (const float*)d_in[6];
    const float* b_qkv  = (const float*)d_in[7];
    const float* w_o    = (const float*)d_in[8];
    const float* b_o    = (const float*)d_in[9];
    const float* w_fc1  = (const float*)d_in[10];
    const float* b_fc1  = (const float*)d_in[11];
    const float* w_fc2  = (const float*)d_in[12];
    const float* b_fc2  = (const float*)d_in[13];
    float* out = (float*)d_out;

    __half *xn, *qkvb, *attnb, *fc1b, *wc;
    float *x2;
    cudaGetSymbolAddress((void**)&xn,    g_xn);
    cudaGetSymbolAddress((void**)&qkvb,  g_qkv);
    cudaGetSymbolAddress((void**)&attnb, g_attn);
    cudaGetSymbolAddress((void**)&x2,    g_x2);
    cudaGetSymbolAddress((void**)&fc1b,  g_fc1);
    cudaGetSymbolAddress((void**)&wc,    g_wc);

    __half* wc_qkv = wc;
    __half* wc_o   = wc + (size_t)3 * 1024 * 1024;
    __half* wc_fc1 = wc + (size_t)4 * 1024 * 1024;
    __half* wc_fc2 = wc + (size_t)8 * 1024 * 1024;

    cudaFuncSetAttribute(gemm_mma<0>, cudaFuncAttributeMaxDynamicSharedMemorySize, GEMM_SMEM);
    cudaFuncSetAttribute(gemm_mma<1>, cudaFuncAttributeMaxDynamicSharedMemorySize, GEMM_SMEM);
    cudaFuncSetAttribute(gemm_mma<2>, cudaFuncAttributeMaxDynamicSharedMemorySize, GEMM_SMEM);
    cudaFuncSetAttribute(attn_tc, cudaFuncAttributeMaxDynamicSharedMemorySize, ATT_SMEM);

    // 0. Convert weights to fp16 once per call
    cvt_kernel<<<(E3 * EE / 8 + 255) / 256, 256>>>(w_qkv, wc_qkv, E3 * EE);
    cvt_kernel<<<(EE * EE / 8 + 255) / 256, 256>>>(w_o,   wc_o,   EE * EE);
    cvt_kernel<<<(FFD * EE / 8 + 255) / 256, 256>>>(w_fc1, wc_fc1, FFD * EE);
    cvt_kernel<<<(EE * FFD / 8 + 255) / 256, 256>>>(w_fc2, wc_fc2, EE * FFD);

    // 1. LN1 -> fp16
    ln_kernel<<<MM, 256>>>(x, ln1_g, ln1_b, xn);
    // 2. QKV projection -> fp16
    gemm_mma<0><<<dim3(E3 / BN, MM / BM), 256, GEMM_SMEM>>>(xn, wc_qkv, b_qkv, nullptr,
                                                            qkvb, MM, E3, EE);
    // 3. FP16 tensor-core attention -> fp16
    attn_tc<<<dim3(SS / 128, BB * HH), 256, ATT_SMEM>>>(qkvb, td, attnb);
    // 4. O projection + residual -> fp32
    gemm_mma<1><<<dim3(EE / BN, MM / BM), 256, GEMM_SMEM>>>(attnb, wc_o, b_o, x,
                                                            x2, MM, EE, EE);
    // 5. LN2 -> fp16
    ln_kernel<<<MM, 256>>>(x2, ln2_g, ln2_b, xn);
    // 6. FC1 + GELU -> fp16
    gemm_mma<2><<<dim3(FFD / BN, MM / BM), 256, GEMM_SMEM>>>(xn, wc_fc1, b_fc1, nullptr,
                                                             fc1b, MM, FFD, EE);
    // 7. FC2 + residual -> fp32 out
    gemm_mma<1><<<dim3(EE / BN, MM / BM), 256, GEMM_SMEM>>>(fc1b, wc_fc2, b_fc2, x2,
                                                            out, MM, EE, FFD);
}

// round 11
// speedup vs baseline: 2.0137x; 1.0381x over previous
#include <cuda_runtime.h>
#include <cuda_fp16.h>
#include <math.h>
#include <stdint.h>

// Problem constants
#define BB 4
#define SS 2048
#define EE 1024
#define HH 16
#define DH 64
#define FFD 4096
#define MM (BB * SS)          // 8192 tokens
#define E3 (3 * EE)           // 3072

// ---------------------------------------------------------------------------
// Scratch buffers (device globals; allocation-free)
// ---------------------------------------------------------------------------
__device__ __align__(128) __half g_xn[(size_t)MM * EE];     // LN out (fp16)
__device__ __align__(128) __half g_qkv[(size_t)MM * E3];    // QKV (fp16)
__device__ __align__(128) __half g_attn[(size_t)MM * EE];   // attention out (fp16)
__device__ __align__(128) float  g_x2[(size_t)MM * EE];     // residual (fp32)
__device__ __align__(128) __half g_fc1[(size_t)MM * FFD];   // gelu(fc1) (fp16)
// fp16 weights: qkv(3M) | o(1M) | fc1(4M) | fc2(4M)
__device__ __align__(128) __half g_wc[(size_t)12 * 1024 * 1024];

// ---------------------------------------------------------------------------
// Helpers
// ---------------------------------------------------------------------------
__device__ __forceinline__ uint32_t smem_u32(const void* p) {
    uint32_t a;
    asm("{ .reg .u64 t; cvta.to.shared.u64 t, %1; cvt.u32.u64 %0, t; }"
        : "=r"(a) : "l"(p));
    return a;
}
__device__ __forceinline__ void cp16(uint32_t s, const void* g) {
    asm volatile("cp.async.cg.shared.global [%0], [%1], 16;" :: "r"(s), "l"(g));
}
#define CP_COMMIT asm volatile("cp.async.commit_group;" ::: "memory")
#define CP_WAIT1  asm volatile("cp.async.wait_group 1;" ::: "memory")

// fp16 mma m16n8k16, fp32 accumulate
__device__ __forceinline__ void mmah(float c[4], const uint32_t a[4],
                                     uint32_t b0, uint32_t b1) {
    asm volatile(
        "mma.sync.aligned.m16n8k16.row.col.f32.f16.f16.f32 "
        "{%0,%1,%2,%3}, {%4,%5,%6,%7}, {%8,%9}, {%0,%1,%2,%3};"
        : "+f"(c[0]), "+f"(c[1]), "+f"(c[2]), "+f"(c[3])
        : "r"(a[0]), "r"(a[1]), "r"(a[2]), "r"(a[3]), "r"(b0), "r"(b1));
}
#define LDSM4(r, addr) \
    asm volatile("ldmatrix.sync.aligned.m8n8.x4.shared.b16 {%0,%1,%2,%3}, [%4];" \
        : "=r"((r)[0]), "=r"((r)[1]), "=r"((r)[2]), "=r"((r)[3]) : "r"(addr))
#define LDSM4T(r, addr) \
    asm volatile("ldmatrix.sync.aligned.m8n8.x4.trans.shared.b16 {%0,%1,%2,%3}, [%4];" \
        : "=r"((r)[0]), "=r"((r)[1]), "=r"((r)[2]), "=r"((r)[3]) : "r"(addr))

// ---------------------------------------------------------------------------
// Weight convert fp32 -> fp16
// ---------------------------------------------------------------------------
__global__ void __launch_bounds__(256) cvt_kernel(const float* __restrict__ in,
                                                  __half* __restrict__ out, int n) {
    int i = (blockIdx.x * 256 + threadIdx.x) * 8;
    if (i < n) {
        float4 v0 = *(const float4*)(in + i);
        float4 v1 = *(const float4*)(in + i + 4);
        __half2 h[4];
        h[0] = __floats2half2_rn(v0.x, v0.y);
        h[1] = __floats2half2_rn(v0.z, v0.w);
        h[2] = __floats2half2_rn(v1.x, v1.y);
        h[3] = __floats2half2_rn(v1.z, v1.w);
        *(uint2*)(out + i)     = make_uint2(*(uint32_t*)&h[0], *(uint32_t*)&h[1]);
        *(uint2*)(out + i + 4) = make_uint2(*(uint32_t*)&h[2], *(uint32_t*)&h[3]);
    }
}

// ---------------------------------------------------------------------------
// FP16 mma.sync GEMM NT: C[m,n] = sum_k A[m,k]*W[n,k] (+epilogue)
//   EPI 0: + bias -> half (QKV)
//   EPI 1: + bias + residual -> float
//   EPI 2: + bias, exact GELU -> half
// CTA 128x128x64(halves), 8 warps (4Mx2N), warp 32x64,
// 3-stage cp.async ring, ONE __syncthreads per K-iteration.
// ---------------------------------------------------------------------------
#define BM 128
#define BN 128
#define BK 64                          // K-tile in halves
#define SROWB 144                      // padded row stride in BYTES
#define ASTGB (BM * SROWB)             // 18432 B
#define STGB (2 * ASTGB)               // 36864 B per stage
#define NSTG 3
#define GEMM_SMEM (NSTG * STGB)        // 110592 B

template <int EPI>
__global__ void __launch_bounds__(256, 2) gemm_mma(
    const __half* __restrict__ A, const __half* __restrict__ W,
    const float* __restrict__ bias, const float* __restrict__ res,
    void* __restrict__ Cv, int M, int N, int K)
{
    extern __shared__ char smemraw[];
    const int tid = threadIdx.x;
    const int bm = blockIdx.y * BM;
    const int bn = blockIdx.x * BN;
    const uint32_t sbase = smem_u32(smemraw);

    const int w = tid >> 5, lane = tid & 31;
    const int t = lane & 3;
    const int g = lane >> 2;
    const int wm = (w & 3) * 32;       // 4 M warps
    const int wn = (w >> 2) * 64;      // 2 N warps

    const uint32_t aLd = (wm + (lane & 15)) * SROWB + ((lane >> 4) << 4);
    const uint32_t bLd = (wn + (lane & 7) + ((lane >> 4) << 3)) * SROWB
                         + (((lane >> 3) & 1) << 4);

    const __half* Ag = A + (size_t)bm * K;
    const __half* Wg = W + (size_t)bn * K;

    float acc[2][8][4];
    #pragma unroll
    for (int mi = 0; mi < 2; mi++)
        #pragma unroll
        for (int ni = 0; ni < 8; ni++)
            #pragma unroll
            for (int j = 0; j < 4; j++) acc[mi][ni][j] = 0.0f;

    auto load_tile = [&](int stg, int kt) {
        const uint32_t dA = sbase + stg * STGB;
        const uint32_t dB = dA + ASTGB;
        const int kofs = kt * BK;
        #pragma unroll
        for (int i = 0; i < 4; i++) {
            int chunk = tid + i * 256;
            int r = chunk >> 3, c = chunk & 7;
            cp16(dA + r * SROWB + c * 16, Ag + (size_t)r * K + kofs + c * 8);
        }
        #pragma unroll
        for (int i = 0; i < 4; i++) {
            int chunk = tid + i * 256;
            int r = chunk >> 3, c = chunk & 7;
            cp16(dB + r * SROWB + c * 16, Wg + (size_t)r * K + kofs + c * 8);
        }
    };

    const int nk = K / BK;
    load_tile(0, 0); CP_COMMIT;
    load_tile(1, 1); CP_COMMIT;

    for (int kt = 0; kt < nk; kt++) {
        const int s = kt % NSTG;
        CP_WAIT1;               // tile kt landed (this thread)
        __syncthreads();        // tile kt visible to all; stage (kt+2)%3 freed
        const int nxt = kt + 2;
        if (nxt < nk) load_tile(nxt % NSTG, nxt);
        CP_COMMIT;              // unconditional: keeps group accounting aligned

        const uint32_t aBase = sbase + s * STGB + aLd;
        const uint32_t bBase = sbase + s * STGB + ASTGB + bLd;

        #pragma unroll
        for (int ks = 0; ks < 4; ks++) {
            const uint32_t ko = ks * 32;
            uint32_t a0[4], a1[4], bq[4][4];
            LDSM4(a0, aBase + ko);
            LDSM4(a1, aBase + 16 * SROWB + ko);
            #pragma unroll
            for (int p = 0; p < 4; p++)
                LDSM4(bq[p], bBase + p * 16 * SROWB + ko);
            #pragma unroll
            for (int p = 0; p < 4; p++) {
                mmah(acc[0][2 * p],     a0, bq[p][0], bq[p][1]);
                mmah(acc[0][2 * p + 1], a0, bq[p][2], bq[p][3]);
                mmah(acc[1][2 * p],     a1, bq[p][0], bq[p][1]);
                mmah(acc[1][2 * p + 1], a1, bq[p][2], bq[p][3]);
            }
        }
    }

    // epilogue
    float bb[8][2];
    #pragma unroll
    for (int ni = 0; ni < 8; ni++) {
        int col = bn + wn + ni * 8 + t * 2;
        bb[ni][0] = __ldg(bias + col);
        bb[ni][1] = __ldg(bias + col + 1);
    }
    #pragma unroll
    for (int mi = 0; mi < 2; mi++) {
        #pragma unroll
        for (int h = 0; h < 2; h++) {
            const int row = bm + wm + mi * 16 + g + h * 8;
            #pragma unroll
            for (int ni = 0; ni < 8; ni++) {
                const int col = bn + wn + ni * 8 + t * 2;
                float o0 = acc[mi][ni][h * 2 + 0] + bb[ni][0];
                float o1 = acc[mi][ni][h * 2 + 1] + bb[ni][1];
                if (EPI == 0) {
                    *(__half2*)((__half*)Cv + (size_t)row * N + col) =
                        __floats2half2_rn(o0, o1);
                } else if (EPI == 1) {
                    const float2 rv = *(const float2*)(res + (size_t)row * N + col);
                    *(float2*)((float*)Cv + (size_t)row * N + col) =
                        make_float2(o0 + rv.x, o1 + rv.y);
                } else {
                    o0 = 0.5f * o0 * (1.0f + erff(o0 * 0.70710678118654752f));
                    o1 = 0.5f * o1 * (1.0f + erff(o1 * 0.70710678118654752f));
                    *(__half2*)((__half*)Cv + (size_t)row * N + col) =
                        __floats2half2_rn(o0, o1);
                }
            }
        }
    }
}

// ---------------------------------------------------------------------------
// LayerNorm: one block per token row of 1024; fp16 output
// ---------------------------------------------------------------------------
__global__ void __launch_bounds__(256) ln_kernel(const float* __restrict__ x,
                                                 const float* __restrict__ g,
                                                 const float* __restrict__ b,
                                                 __half* __restrict__ out) {
    int row = blockIdx.x;
    const float4* xr = (const float4*)(x + (size_t)row * EE);
    float4 v = xr[threadIdx.x];
    float s  = v.x + v.y + v.z + v.w;
    float sq = v.x * v.x + v.y * v.y + v.z * v.z + v.w * v.w;
    #pragma unroll
    for (int o = 16; o; o >>= 1) {
        s  += __shfl_xor_sync(0xffffffffu, s,  o);
        sq += __shfl_xor_sync(0xffffffffu, sq, o);
    }
    __shared__ float ss[8], ssq[8];
    int w = threadIdx.x >> 5, ln = threadIdx.x & 31;
    if (ln == 0) { ss[w] = s; ssq[w] = sq; }
    __syncthreads();
    if (w == 0) {
        s  = (ln < 8) ? ss[ln]  : 0.0f;
        sq = (ln < 8) ? ssq[ln] : 0.0f;
        #pragma unroll
        for (int o = 4; o; o >>= 1) {
            s  += __shfl_xor_sync(0xffffffffu, s,  o);
            sq += __shfl_xor_sync(0xffffffffu, sq, o);
        }
        if (ln == 0) { ss[0] = s; ssq[0] = sq; }
    }
    __syncthreads();
    float mean = ss[0] * (1.0f / EE);
    float var  = ssq[0] * (1.0f / EE) - mean * mean;
    float rstd = rsqrtf(var + 1e-5f);
    int c = threadIdx.x * 4;
    float4 gg = *(const float4*)(g + c);
    float4 bb = *(const float4*)(b + c);
    __half2 h0 = __floats2half2_rn((v.x - mean) * rstd * gg.x + bb.x,
                                   (v.y - mean) * rstd * gg.y + bb.y);
    __half2 h1 = __floats2half2_rn((v.z - mean) * rstd * gg.z + bb.z,
                                   (v.w - mean) * rstd * gg.w + bb.w);
    *(uint2*)(out + (size_t)row * EE + c) =
        make_uint2(*(uint32_t*)&h0, *(uint32_t*)&h1);
}

// ---------------------------------------------------------------------------
// FP16 tensor-core flash attention, mask (j > i) || (j % TD == TD-1).
// 128-query CTA tile, 64-kv chunks, 8 warps x 16 q-rows, m16n8k16.
// QK via ldmatrix; PV B-operand via ldmatrix.trans (vLd mapping verified).
// ---------------------------------------------------------------------------
#define AS2 72                          // smem row stride (halves) = 144 B
#define ATT_SMEM ((128 + 64 + 64 + 128) * AS2 * 2)

__global__ void __launch_bounds__(256, 2) attn_tc(const __half* __restrict__ qkv,
                                                  const int* __restrict__ tdp,
                                                  __half* __restrict__ out) {
    extern __shared__ char smemraw[];
    __half* Qs = (__half*)smemraw;     // [128][AS2]
    __half* Ks = Qs + 128 * AS2;       // [64][AS2]
    __half* Vs = Ks + 64 * AS2;        // [64][AS2]
    __half* Ps = Vs + 64 * AS2;        // [128][AS2]

    const int qb = blockIdx.x, bh = blockIdx.y;
    const int b = bh >> 4, h = bh & 15;
    const int TD = tdp[0];
    const int tid = threadIdx.x, w = tid >> 5, lane = tid & 31;
    const int g = lane >> 2, t = lane & 3;

    const size_t base = (size_t)b * SS * E3 + (size_t)h * DH;

    const uint32_t qLd = smem_u32(Qs) +
        (w * 16 + (lane & 15)) * (AS2 * 2) + ((lane >> 4) << 4);
    const uint32_t kLd = smem_u32(Ks) +
        ((lane & 7) + ((lane >> 4) << 3)) * (AS2 * 2) + (((lane >> 3) & 1) << 4);
    const uint32_t pLd = smem_u32(Ps) +
        (w * 16 + (lane & 15)) * (AS2 * 2) + ((lane >> 4) << 4);
    // V trans-fragment: lanes 0-7 -> kv rows 0-7 @ d0, 8-15 -> rows 8-15 @ d0,
    // 16-23 -> rows 0-7 @ d8, 24-31 -> rows 8-15 @ d8
    const uint32_t vLd = smem_u32(Vs) +
        (lane & 15) * (AS2 * 2) + ((lane >> 4) << 4);

    // load Q tile 128x64 halves (uint4 = 8 halves per chunk, 8 chunks/row)
    for (int i = tid; i < 128 * 8; i += 256) {
        int r = i >> 3, c = (i & 7) * 8;
        *(uint4*)(Qs + r * AS2 + c) =
            *(const uint4*)(qkv + base + (size_t)(qb * 128 + r) * E3 + c);
    }

    float m0 = -1e30f, m1 = -1e30f, l0 = 0.0f, l1 = 0.0f;
    float o[8][4];
    #pragma unroll
    for (int ni = 0; ni < 8; ni++)
        #pragma unroll
        for (int j = 0; j < 4; j++) o[ni][j] = 0.0f;

    const int ig0 = qb * 128 + w * 16 + g;
    const int ig1 = ig0 + 8;
    const int nkt = 2 * qb + 2;

    for (int kb = 0; kb < nkt; kb++) {
        __syncthreads();
        for (int i = tid; i < 64 * 8; i += 256) {
            int r = i >> 3, c = (i & 7) * 8;
            size_t off = base + (size_t)(kb * 64 + r) * E3 + c;
            *(uint4*)(Ks + r * AS2 + c) = *(const uint4*)(qkv + off + EE);
            *(uint4*)(Vs + r * AS2 + c) = *(const uint4*)(qkv + off + 2 * EE);
        }
        __syncthreads();

        // --- scores = Q @ K^T ---
        float s[8][4];
        #pragma unroll
        for (int ni = 0; ni < 8; ni++)
            #pragma unroll
            for (int j = 0; j < 4; j++) s[ni][j] = 0.0f;

        #pragma unroll
        for (int ks = 0; ks < 4; ks++) {
            const uint32_t ko = ks * 32;
            uint32_t aq[4];
            LDSM4(aq, qLd + ko);
            #pragma unroll
            for (int p = 0; p < 4; p++) {
                uint32_t bk[4];
                LDSM4(bk, kLd + p * 16 * (AS2 * 2) + ko);
                mmah(s[2 * p],     aq, bk[0], bk[1]);
                mmah(s[2 * p + 1], aq, bk[2], bk[3]);
            }
        }

        // --- mask + scale + online softmax ---
        float rm0 = -1e30f, rm1 = -1e30f;
        #pragma unroll
        for (int ni = 0; ni < 8; ni++) {
            #pragma unroll
            for (int j = 0; j < 2; j++) {
                const int col = kb * 64 + ni * 8 + t * 2 + j;
                const bool dead = ((col % TD) == TD - 1);
                float v0 = (dead || col > ig0) ? -1e30f : s[ni][j] * 0.125f;
                float v1 = (dead || col > ig1) ? -1e30f : s[ni][2 + j] * 0.125f;
                s[ni][j] = v0; s[ni][2 + j] = v1;
                rm0 = fmaxf(rm0, v0); rm1 = fmaxf(rm1, v1);
            }
        }
        #pragma unroll
        for (int ofs = 1; ofs < 4; ofs <<= 1) {
            rm0 = fmaxf(rm0, __shfl_xor_sync(0xffffffffu, rm0, ofs));
            rm1 = fmaxf(rm1, __shfl_xor_sync(0xffffffffu, rm1, ofs));
        }
        const float nm0 = fmaxf(m0, rm0), nm1 = fmaxf(m1, rm1);
        const float a0 = __expf(m0 - nm0), a1 = __expf(m1 - nm1);
        m0 = nm0; m1 = nm1;

        float rs0 = 0.0f, rs1 = 0.0f;
        __half* pR0 = Ps + (w * 16 + g) * AS2;
        __half* pR1 = pR0 + 8 * AS2;
        #pragma unroll
        for (int ni = 0; ni < 8; ni++) {
            float p00 = __expf(s[ni][0] - m0), p01 = __expf(s[ni][1] - m0);
            float p10 = __expf(s[ni][2] - m1), p11 = __expf(s[ni][3] - m1);
            rs0 += p00 + p01; rs1 += p10 + p11;
            const int c = ni * 8 + t * 2;
            *(__half2*)(pR0 + c) = __floats2half2_rn(p00, p01);
            *(__half2*)(pR1 + c) = __floats2half2_rn(p10, p11);
        }
        #pragma unroll
        for (int ofs = 1; ofs < 4; ofs <<= 1) {
            rs0 += __shfl_xor_sync(0xffffffffu, rs0, ofs);
            rs1 += __shfl_xor_sync(0xffffffffu, rs1, ofs);
        }
        l0 = l0 * a0 + rs0;
        l1 = l1 * a1 + rs1;
        #pragma unroll
        for (int ni = 0; ni < 8; ni++) {
            o[ni][0] *= a0; o[ni][1] *= a0;
            o[ni][2] *= a1; o[ni][3] *= a1;
        }
        __syncwarp();

        // --- O += P @ V (V B-fragment via ldmatrix.trans) ---
        #pragma unroll
        for (int ks = 0; ks < 4; ks++) {
            const uint32_t ko = ks * 32;
            uint32_t a[4];
            LDSM4(a, pLd + ko);
            const uint32_t vBase = vLd + ks * 16 * (AS2 * 2);
            #pragma unroll
            for (int db = 0; db < 4; db++) {
                uint32_t bv[4];
                LDSM4T(bv, vBase + db * 32);
                mmah(o[2 * db],     a, bv[0], bv[1]);
                mmah(o[2 * db + 1], a, bv[2], bv[3]);
            }
        }
    }

    // epilogue -> fp16 (feeds O-projection fp16 GEMM)
    const float inv0 = 1.0f / l0, inv1 = 1.0f / l1;
    const size_t r0o = ((size_t)(b * SS + qb * 128 + w * 16 + g)) * EE + h * DH;
    const size_t r1o = r0o + 8 * EE;
    #pragma unroll
    for (int ni = 0; ni < 8; ni++) {
        const int c = ni * 8 + t * 2;
        *(__half2*)(out + r0o + c) = __floats2half2_rn(o[ni][0] * inv0, o[ni][1] * inv0);
        *(__half2*)(out + r1o + c) = __floats2half2_rn(o[ni][2] * inv1, o[ni][3] * inv1);
    }
}

// ---------------------------------------------------------------------------
// Launch
// ---------------------------------------------------------------------------
extern "C" void kernel_launch(void* const* d_in, const int* in_sizes, int n_in,
                              void* d_out, int out_size) {
    const float* x      = (const float*)d_in[0];
    const int*   td     = (const int*)d_in[1];
    const float* ln1_g  = (const float*)d_in[2];
    const float* ln1_b  = (const float*)d_in[3];
    const float* ln2_g  = (const float*)d_in[4];
    const float* ln2_b  = (const float*)d_in[5];
    const float* w_qkv  = (const float*)d_in[6];
    const float* b_qkv  = (const float*)d_in[7];
    const float* w_o    = (const float*)d_in[8];
    const float* b_o    = (const float*)d_in[9];
    const float* w_fc1  = (const float*)d_in[10];
    const float* b_fc1  = (const float*)d_in[11];
    const float* w_fc2  = (const float*)d_in[12];
    const float* b_fc2  = (const float*)d_in[13];
    float* out = (float*)d_out;

    __half *xn, *qkvb, *attnb, *fc1b, *wc;
    float *x2;
    cudaGetSymbolAddress((void**)&xn,    g_xn);
    cudaGetSymbolAddress((void**)&qkvb,  g_qkv);
    cudaGetSymbolAddress((void**)&attnb, g_attn);
    cudaGetSymbolAddress((void**)&x2,    g_x2);
    cudaGetSymbolAddress((void**)&fc1b,  g_fc1);
    cudaGetSymbolAddress((void**)&wc,    g_wc);

    __half* wc_qkv = wc;
    __half* wc_o   = wc + (size_t)3 * 1024 * 1024;
    __half* wc_fc1 = wc + (size_t)4 * 1024 * 1024;
    __half* wc_fc2 = wc + (size_t)8 * 1024 * 1024;

    cudaFuncSetAttribute(gemm_mma<0>, cudaFuncAttributeMaxDynamicSharedMemorySize, GEMM_SMEM);
    cudaFuncSetAttribute(gemm_mma<1>, cudaFuncAttributeMaxDynamicSharedMemorySize, GEMM_SMEM);
    cudaFuncSetAttribute(gemm_mma<2>, cudaFuncAttributeMaxDynamicSharedMemorySize, GEMM_SMEM);
    cudaFuncSetAttribute(attn_tc, cudaFuncAttributeMaxDynamicSharedMemorySize, ATT_SMEM);

    // 0. Convert weights to fp16 once per call
    cvt_kernel<<<(E3 * EE / 8 + 255) / 256, 256>>>(w_qkv, wc_qkv, E3 * EE);
    cvt_kernel<<<(EE * EE / 8 + 255) / 256, 256>>>(w_o,   wc_o,   EE * EE);
    cvt_kernel<<<(FFD * EE / 8 + 255) / 256, 256>>>(w_fc1, wc_fc1, FFD * EE);
    cvt_kernel<<<(EE * FFD / 8 + 255) / 256, 256>>>(w_fc2, wc_fc2, EE * FFD);

    // 1. LN1 -> fp16
    ln_kernel<<<MM, 256>>>(x, ln1_g, ln1_b, xn);
    // 2. QKV projection -> fp16
    gemm_mma<0><<<dim3(E3 / BN, MM / BM), 256, GEMM_SMEM>>>(xn, wc_qkv, b_qkv, nullptr,
                                                            qkvb, MM, E3, EE);
    // 3. FP16 tensor-core attention -> fp16
    attn_tc<<<dim3(SS / 128, BB * HH), 256, ATT_SMEM>>>(qkvb, td, attnb);
    // 4. O projection + residual -> fp32
    gemm_mma<1><<<dim3(EE / BN, MM / BM), 256, GEMM_SMEM>>>(attnb, wc_o, b_o, x,
                                                            x2, MM, EE, EE);
    // 5. LN2 -> fp16
    ln_kernel<<<MM, 256>>>(x2, ln2_g, ln2_b, xn);
    // 6. FC1 + GELU -> fp16
    gemm_mma<2><<<dim3(FFD / BN, MM / BM), 256, GEMM_SMEM>>>(xn, wc_fc1, b_fc1, nullptr,
                                                             fc1b, MM, FFD, EE);
    // 7. FC2 + residual -> fp32 out
    gemm_mma<1><<<dim3(EE / BN, MM / BM), 256, GEMM_SMEM>>>(fc1b, wc_fc2, b_fc2, x2,
                                                            out, MM, EE, FFD);
}

// round 12
// speedup vs baseline: 2.0672x; 1.0266x over previous
#include <cuda_runtime.h>
#include <cuda_fp16.h>
#include <math.h>
#include <stdint.h>

// Problem constants
#define BB 4
#define SS 2048
#define EE 1024
#define HH 16
#define DH 64
#define FFD 4096
#define MM (BB * SS)          // 8192 tokens
#define E3 (3 * EE)           // 3072

// ---------------------------------------------------------------------------
// Scratch buffers (device globals; allocation-free)
// ---------------------------------------------------------------------------
__device__ __align__(128) __half g_xn[(size_t)MM * EE];     // LN out (fp16)
__device__ __align__(128) __half g_qkv[(size_t)MM * E3];    // QKV (fp16)
__device__ __align__(128) __half g_attn[(size_t)MM * EE];   // attention out (fp16)
__device__ __align__(128) float  g_x2[(size_t)MM * EE];     // residual (fp32)
__device__ __align__(128) __half g_fc1[(size_t)MM * FFD];   // gelu(fc1) (fp16)
// fp16 weights: qkv(3M) | o(1M) | fc1(4M) | fc2(4M)
__device__ __align__(128) __half g_wc[(size_t)12 * 1024 * 1024];

// ---------------------------------------------------------------------------
// Helpers
// ---------------------------------------------------------------------------
__device__ __forceinline__ uint32_t smem_u32(const void* p) {
    uint32_t a;
    asm("{ .reg .u64 t; cvta.to.shared.u64 t, %1; cvt.u32.u64 %0, t; }"
        : "=r"(a) : "l"(p));
    return a;
}
__device__ __forceinline__ void cp16(uint32_t s, const void* g) {
    asm volatile("cp.async.cg.shared.global [%0], [%1], 16;" :: "r"(s), "l"(g));
}
#define CP_COMMIT asm volatile("cp.async.commit_group;" ::: "memory")
#define CP_WAIT1  asm volatile("cp.async.wait_group 1;" ::: "memory")
#define CP_WAIT0  asm volatile("cp.async.wait_group 0;" ::: "memory")

// fp16 mma m16n8k16, fp32 accumulate
__device__ __forceinline__ void mmah(float c[4], const uint32_t a[4],
                                     uint32_t b0, uint32_t b1) {
    asm volatile(
        "mma.sync.aligned.m16n8k16.row.col.f32.f16.f16.f32 "
        "{%0,%1,%2,%3}, {%4,%5,%6,%7}, {%8,%9}, {%0,%1,%2,%3};"
        : "+f"(c[0]), "+f"(c[1]), "+f"(c[2]), "+f"(c[3])
        : "r"(a[0]), "r"(a[1]), "r"(a[2]), "r"(a[3]), "r"(b0), "r"(b1));
}
#define LDSM4(r, addr) \
    asm volatile("ldmatrix.sync.aligned.m8n8.x4.shared.b16 {%0,%1,%2,%3}, [%4];" \
        : "=r"((r)[0]), "=r"((r)[1]), "=r"((r)[2]), "=r"((r)[3]) : "r"(addr))
#define LDSM4T(r, addr) \
    asm volatile("ldmatrix.sync.aligned.m8n8.x4.trans.shared.b16 {%0,%1,%2,%3}, [%4];" \
        : "=r"((r)[0]), "=r"((r)[1]), "=r"((r)[2]), "=r"((r)[3]) : "r"(addr))

// ---------------------------------------------------------------------------
// Fused weight convert fp32 -> fp16 (all 4 weight matrices, one launch)
//   layout in g_wc: qkv [0,3M) | o [3M,4M) | fc1 [4M,8M) | fc2 [8M,12M)
// ---------------------------------------------------------------------------
#define M1 (1024 * 1024)
__global__ void __launch_bounds__(256) cvt_all_kernel(
    const float* __restrict__ w_qkv, const float* __restrict__ w_o,
    const float* __restrict__ w_fc1, const float* __restrict__ w_fc2,
    __half* __restrict__ out) {
    int i = (blockIdx.x * 256 + threadIdx.x) * 8;   // [0, 12M)
    const float* src;
    int ofs;
    if (i < 3 * M1)       { src = w_qkv; ofs = i; }
    else if (i < 4 * M1)  { src = w_o;   ofs = i - 3 * M1; }
    else if (i < 8 * M1)  { src = w_fc1; ofs = i - 4 * M1; }
    else                  { src = w_fc2; ofs = i - 8 * M1; }
    float4 v0 = *(const float4*)(src + ofs);
    float4 v1 = *(const float4*)(src + ofs + 4);
    __half2 h[4];
    h[0] = __floats2half2_rn(v0.x, v0.y);
    h[1] = __floats2half2_rn(v0.z, v0.w);
    h[2] = __floats2half2_rn(v1.x, v1.y);
    h[3] = __floats2half2_rn(v1.z, v1.w);
    *(uint2*)(out + i)     = make_uint2(*(uint32_t*)&h[0], *(uint32_t*)&h[1]);
    *(uint2*)(out + i + 4) = make_uint2(*(uint32_t*)&h[2], *(uint32_t*)&h[3]);
}

// ---------------------------------------------------------------------------
// FP16 mma.sync GEMM NT: C[m,n] = sum_k A[m,k]*W[n,k] (+epilogue)
//   EPI 0: + bias -> half (QKV)
//   EPI 1: + bias + residual -> float
//   EPI 2: + bias, exact GELU -> half
// CTA 128x128x64(halves), 8 warps (4Mx2N), warp 32x64,
// 3-stage cp.async ring, ONE __syncthreads per K-iteration.
// ---------------------------------------------------------------------------
#define BM 128
#define BN 128
#define BK 64                          // K-tile in halves
#define SROWB 144                      // padded row stride in BYTES
#define ASTGB (BM * SROWB)             // 18432 B
#define STGB (2 * ASTGB)               // 36864 B per stage
#define NSTG 3
#define GEMM_SMEM (NSTG * STGB)        // 110592 B

template <int EPI>
__global__ void __launch_bounds__(256, 2) gemm_mma(
    const __half* __restrict__ A, const __half* __restrict__ W,
    const float* __restrict__ bias, const float* __restrict__ res,
    void* __restrict__ Cv, int M, int N, int K)
{
    extern __shared__ char smemraw[];
    const int tid = threadIdx.x;
    const int bm = blockIdx.y * BM;
    const int bn = blockIdx.x * BN;
    const uint32_t sbase = smem_u32(smemraw);

    const int w = tid >> 5, lane = tid & 31;
    const int t = lane & 3;
    const int g = lane >> 2;
    const int wm = (w & 3) * 32;       // 4 M warps
    const int wn = (w >> 2) * 64;      // 2 N warps

    const uint32_t aLd = (wm + (lane & 15)) * SROWB + ((lane >> 4) << 4);
    const uint32_t bLd = (wn + (lane & 7) + ((lane >> 4) << 3)) * SROWB
                         + (((lane >> 3) & 1) << 4);

    const __half* Ag = A + (size_t)bm * K;
    const __half* Wg = W + (size_t)bn * K;

    float acc[2][8][4];
    #pragma unroll
    for (int mi = 0; mi < 2; mi++)
        #pragma unroll
        for (int ni = 0; ni < 8; ni++)
            #pragma unroll
            for (int j = 0; j < 4; j++) acc[mi][ni][j] = 0.0f;

    auto load_tile = [&](int stg, int kt) {
        const uint32_t dA = sbase + stg * STGB;
        const uint32_t dB = dA + ASTGB;
        const int kofs = kt * BK;
        #pragma unroll
        for (int i = 0; i < 4; i++) {
            int chunk = tid + i * 256;
            int r = chunk >> 3, c = chunk & 7;
            cp16(dA + r * SROWB + c * 16, Ag + (size_t)r * K + kofs + c * 8);
        }
        #pragma unroll
        for (int i = 0; i < 4; i++) {
            int chunk = tid + i * 256;
            int r = chunk >> 3, c = chunk & 7;
            cp16(dB + r * SROWB + c * 16, Wg + (size_t)r * K + kofs + c * 8);
        }
    };

    const int nk = K / BK;
    load_tile(0, 0); CP_COMMIT;
    load_tile(1, 1); CP_COMMIT;

    for (int kt = 0; kt < nk; kt++) {
        const int s = kt % NSTG;
        CP_WAIT1;               // tile kt landed (this thread)
        __syncthreads();        // tile kt visible to all; stage (kt+2)%3 freed
        const int nxt = kt + 2;
        if (nxt < nk) load_tile(nxt % NSTG, nxt);
        CP_COMMIT;              // unconditional: keeps group accounting aligned

        const uint32_t aBase = sbase + s * STGB + aLd;
        const uint32_t bBase = sbase + s * STGB + ASTGB + bLd;

        #pragma unroll
        for (int ks = 0; ks < 4; ks++) {
            const uint32_t ko = ks * 32;
            uint32_t a0[4], a1[4], bq[4][4];
            LDSM4(a0, aBase + ko);
            LDSM4(a1, aBase + 16 * SROWB + ko);
            #pragma unroll
            for (int p = 0; p < 4; p++)
                LDSM4(bq[p], bBase + p * 16 * SROWB + ko);
            #pragma unroll
            for (int p = 0; p < 4; p++) {
                mmah(acc[0][2 * p],     a0, bq[p][0], bq[p][1]);
                mmah(acc[0][2 * p + 1], a0, bq[p][2], bq[p][3]);
                mmah(acc[1][2 * p],     a1, bq[p][0], bq[p][1]);
                mmah(acc[1][2 * p + 1], a1, bq[p][2], bq[p][3]);
            }
        }
    }

    // epilogue
    float bb[8][2];
    #pragma unroll
    for (int ni = 0; ni < 8; ni++) {
        int col = bn + wn + ni * 8 + t * 2;
        bb[ni][0] = __ldg(bias + col);
        bb[ni][1] = __ldg(bias + col + 1);
    }
    #pragma unroll
    for (int mi = 0; mi < 2; mi++) {
        #pragma unroll
        for (int h = 0; h < 2; h++) {
            const int row = bm + wm + mi * 16 + g + h * 8;
            #pragma unroll
            for (int ni = 0; ni < 8; ni++) {
                const int col = bn + wn + ni * 8 + t * 2;
                float o0 = acc[mi][ni][h * 2 + 0] + bb[ni][0];
                float o1 = acc[mi][ni][h * 2 + 1] + bb[ni][1];
                if (EPI == 0) {
                    *(__half2*)((__half*)Cv + (size_t)row * N + col) =
                        __floats2half2_rn(o0, o1);
                } else if (EPI == 1) {
                    const float2 rv = *(const float2*)(res + (size_t)row * N + col);
                    *(float2*)((float*)Cv + (size_t)row * N + col) =
                        make_float2(o0 + rv.x, o1 + rv.y);
                } else {
                    o0 = 0.5f * o0 * (1.0f + erff(o0 * 0.70710678118654752f));
                    o1 = 0.5f * o1 * (1.0f + erff(o1 * 0.70710678118654752f));
                    *(__half2*)((__half*)Cv + (size_t)row * N + col) =
                        __floats2half2_rn(o0, o1);
                }
            }
        }
    }
}

// ---------------------------------------------------------------------------
// LayerNorm: one block per token row of 1024; fp16 output
// ---------------------------------------------------------------------------
__global__ void __launch_bounds__(256) ln_kernel(const float* __restrict__ x,
                                                 const float* __restrict__ g,
                                                 const float* __restrict__ b,
                                                 __half* __restrict__ out) {
    int row = blockIdx.x;
    const float4* xr = (const float4*)(x + (size_t)row * EE);
    float4 v = xr[threadIdx.x];
    float s  = v.x + v.y + v.z + v.w;
    float sq = v.x * v.x + v.y * v.y + v.z * v.z + v.w * v.w;
    #pragma unroll
    for (int o = 16; o; o >>= 1) {
        s  += __shfl_xor_sync(0xffffffffu, s,  o);
        sq += __shfl_xor_sync(0xffffffffu, sq, o);
    }
    __shared__ float ss[8], ssq[8];
    int w = threadIdx.x >> 5, ln = threadIdx.x & 31;
    if (ln == 0) { ss[w] = s; ssq[w] = sq; }
    __syncthreads();
    if (w == 0) {
        s  = (ln < 8) ? ss[ln]  : 0.0f;
        sq = (ln < 8) ? ssq[ln] : 0.0f;
        #pragma unroll
        for (int o = 4; o; o >>= 1) {
            s  += __shfl_xor_sync(0xffffffffu, s,  o);
            sq += __shfl_xor_sync(0xffffffffu, sq, o);
        }
        if (ln == 0) { ss[0] = s; ssq[0] = sq; }
    }
    __syncthreads();
    float mean = ss[0] * (1.0f / EE);
    float var  = ssq[0] * (1.0f / EE) - mean * mean;
    float rstd = rsqrtf(var + 1e-5f);
    int c = threadIdx.x * 4;
    float4 gg = *(const float4*)(g + c);
    float4 bb = *(const float4*)(b + c);
    __half2 h0 = __floats2half2_rn((v.x - mean) * rstd * gg.x + bb.x,
                                   (v.y - mean) * rstd * gg.y + bb.y);
    __half2 h1 = __floats2half2_rn((v.z - mean) * rstd * gg.z + bb.z,
                                   (v.w - mean) * rstd * gg.w + bb.w);
    *(uint2*)(out + (size_t)row * EE + c) =
        make_uint2(*(uint32_t*)&h0, *(uint32_t*)&h1);
}

// ---------------------------------------------------------------------------
// FP16 tensor-core flash attention, mask (j > i) || (j % TD == TD-1).
// 128-query CTA tile, 64-kv chunks, 8 warps x 16 q-rows, m16n8k16.
// cp.async double-buffered K/V: load kb+1 overlaps compute kb; 1 sync/iter.
// smem: Q[128] | KV buf0 {K64,V64} | KV buf1 {K64,V64} | P[128], stride 72 h.
// ---------------------------------------------------------------------------
#define AS2 72                          // smem row stride (halves) = 144 B
#define ASB (AS2 * 2)                   // row stride bytes
#define KVB (128 * ASB)                 // one KV buffer (K 64 rows + V 64 rows)
#define ATT_SMEM ((128 + 256 + 128) * ASB)

__global__ void __launch_bounds__(256, 2) attn_tc(const __half* __restrict__ qkv,
                                                  const int* __restrict__ tdp,
                                                  __half* __restrict__ out) {
    extern __shared__ char smemraw[];
    __half* Qs  = (__half*)smemraw;           // [128][AS2]
    __half* KV0 = Qs + 128 * AS2;             // buf0: K[64] then V[64]
    __half* Ps  = KV0 + 2 * 128 * AS2;        // [128][AS2]

    const int qb = blockIdx.x, bh = blockIdx.y;
    const int b = bh >> 4, h = bh & 15;
    const int TD = tdp[0];
    const int tid = threadIdx.x, w = tid >> 5, lane = tid & 31;
    const int g = lane >> 2, t = lane & 3;

    const size_t base = (size_t)b * SS * E3 + (size_t)h * DH;
    const uint32_t kvBase = smem_u32(KV0);

    const uint32_t qLd = smem_u32(Qs) +
        (w * 16 + (lane & 15)) * ASB + ((lane >> 4) << 4);
    const uint32_t kLd0 = kvBase +
        ((lane & 7) + ((lane >> 4) << 3)) * ASB + (((lane >> 3) & 1) << 4);
    const uint32_t vLd0 = kvBase + 64 * ASB +
        (lane & 15) * ASB + ((lane >> 4) << 4);
    const uint32_t pLd = smem_u32(Ps) +
        (w * 16 + (lane & 15)) * ASB + ((lane >> 4) << 4);

    // load Q tile 128x64 halves
    for (int i = tid; i < 128 * 8; i += 256) {
        int r = i >> 3, c = (i & 7) * 8;
        *(uint4*)(Qs + r * AS2 + c) =
            *(const uint4*)(qkv + base + (size_t)(qb * 128 + r) * E3 + c);
    }

    // cp.async KV tile loader: 64 rows x 8 chunks(16B) each for K and V
    auto load_kv = [&](int kb, int buf) {
        const uint32_t dst = kvBase + buf * KVB;
        #pragma unroll
        for (int i = 0; i < 2; i++) {
            int chunk = tid + i * 256;             // 0..511
            int r = chunk >> 3, cB = (chunk & 7) << 4;
            size_t off = base + (size_t)(kb * 64 + r) * E3 + (cB >> 1);
            cp16(dst + r * ASB + cB,            qkv + off + EE);
            cp16(dst + 64 * ASB + r * ASB + cB, qkv + off + 2 * EE);
        }
    };

    float m0 = -1e30f, m1 = -1e30f, l0 = 0.0f, l1 = 0.0f;
    float o[8][4];
    #pragma unroll
    for (int ni = 0; ni < 8; ni++)
        #pragma unroll
        for (int j = 0; j < 4; j++) o[ni][j] = 0.0f;

    const int ig0 = qb * 128 + w * 16 + g;
    const int ig1 = ig0 + 8;
    const int nkt = 2 * qb + 2;

    load_kv(0, 0); CP_COMMIT;

    for (int kb = 0; kb < nkt; kb++) {
        const int buf = kb & 1;
        CP_WAIT0;               // tile kb landed (this thread)
        __syncthreads();        // visible to all; prev readers of buf^1 done
        if (kb + 1 < nkt) load_kv(kb + 1, buf ^ 1);
        CP_COMMIT;

        const uint32_t kLd = kLd0 + buf * KVB;
        const uint32_t vLd = vLd0 + buf * KVB;

        // --- scores = Q @ K^T ---
        float s[8][4];
        #pragma unroll
        for (int ni = 0; ni < 8; ni++)
            #pragma unroll
            for (int j = 0; j < 4; j++) s[ni][j] = 0.0f;

        #pragma unroll
        for (int ks = 0; ks < 4; ks++) {
            const uint32_t ko = ks * 32;
            uint32_t aq[4];
            LDSM4(aq, qLd + ko);
            #pragma unroll
            for (int p = 0; p < 4; p++) {
                uint32_t bk[4];
                LDSM4(bk, kLd + p * 16 * ASB + ko);
                mmah(s[2 * p],     aq, bk[0], bk[1]);
                mmah(s[2 * p + 1], aq, bk[2], bk[3]);
            }
        }

        // --- mask + scale + online softmax ---
        float rm0 = -1e30f, rm1 = -1e30f;
        #pragma unroll
        for (int ni = 0; ni < 8; ni++) {
            #pragma unroll
            for (int j = 0; j < 2; j++) {
                const int col = kb * 64 + ni * 8 + t * 2 + j;
                const bool dead = ((col % TD) == TD - 1);
                float v0 = (dead || col > ig0) ? -1e30f : s[ni][j] * 0.125f;
                float v1 = (dead || col > ig1) ? -1e30f : s[ni][2 + j] * 0.125f;
                s[ni][j] = v0; s[ni][2 + j] = v1;
                rm0 = fmaxf(rm0, v0); rm1 = fmaxf(rm1, v1);
            }
        }
        #pragma unroll
        for (int ofs = 1; ofs < 4; ofs <<= 1) {
            rm0 = fmaxf(rm0, __shfl_xor_sync(0xffffffffu, rm0, ofs));
            rm1 = fmaxf(rm1, __shfl_xor_sync(0xffffffffu, rm1, ofs));
        }
        const float nm0 = fmaxf(m0, rm0), nm1 = fmaxf(m1, rm1);
        const float a0 = __expf(m0 - nm0), a1 = __expf(m1 - nm1);
        m0 = nm0; m1 = nm1;

        float rs0 = 0.0f, rs1 = 0.0f;
        __half* pR0 = Ps + (w * 16 + g) * AS2;
        __half* pR1 = pR0 + 8 * AS2;
        #pragma unroll
        for (int ni = 0; ni < 8; ni++) {
            float p00 = __expf(s[ni][0] - m0), p01 = __expf(s[ni][1] - m0);
            float p10 = __expf(s[ni][2] - m1), p11 = __expf(s[ni][3] - m1);
            rs0 += p00 + p01; rs1 += p10 + p11;
            const int c = ni * 8 + t * 2;
            *(__half2*)(pR0 + c) = __floats2half2_rn(p00, p01);
            *(__half2*)(pR1 + c) = __floats2half2_rn(p10, p11);
        }
        #pragma unroll
        for (int ofs = 1; ofs < 4; ofs <<= 1) {
            rs0 += __shfl_xor_sync(0xffffffffu, rs0, ofs);
            rs1 += __shfl_xor_sync(0xffffffffu, rs1, ofs);
        }
        l0 = l0 * a0 + rs0;
        l1 = l1 * a1 + rs1;
        #pragma unroll
        for (int ni = 0; ni < 8; ni++) {
            o[ni][0] *= a0; o[ni][1] *= a0;
            o[ni][2] *= a1; o[ni][3] *= a1;
        }
        __syncwarp();

        // --- O += P @ V (V B-fragment via ldmatrix.trans) ---
        #pragma unroll
        for (int ks = 0; ks < 4; ks++) {
            const uint32_t ko = ks * 32;
            uint32_t a[4];
            LDSM4(a, pLd + ko);
            const uint32_t vBase = vLd + ks * 16 * ASB;
            #pragma unroll
            for (int db = 0; db < 4; db++) {
                uint32_t bv[4];
                LDSM4T(bv, vBase + db * 32);
                mmah(o[2 * db],     a, bv[0], bv[1]);
                mmah(o[2 * db + 1], a, bv[2], bv[3]);
            }
        }
    }

    // epilogue -> fp16 (feeds O-projection fp16 GEMM)
    const float inv0 = 1.0f / l0, inv1 = 1.0f / l1;
    const size_t r0o = ((size_t)(b * SS + qb * 128 + w * 16 + g)) * EE + h * DH;
    const size_t r1o = r0o + 8 * EE;
    #pragma unroll
    for (int ni = 0; ni < 8; ni++) {
        const int c = ni * 8 + t * 2;
        *(__half2*)(out + r0o + c) = __floats2half2_rn(o[ni][0] * inv0, o[ni][1] * inv0);
        *(__half2*)(out + r1o + c) = __floats2half2_rn(o[ni][2] * inv1, o[ni][3] * inv1);
    }
}

// ---------------------------------------------------------------------------
// Launch
// ---------------------------------------------------------------------------
extern "C" void kernel_launch(void* const* d_in, const int* in_sizes, int n_in,
                              void* d_out, int out_size) {
    const float* x      = (const float*)d_in[0];
    const int*   td     = (const int*)d_in[1];
    const float* ln1_g  = (const float*)d_in[2];
    const float* ln1_b  = (const float*)d_in[3];
    const float* ln2_g  = (const float*)d_in[4];
    const float* ln2_b  = (const float*)d_in[5];
    const float* w_qkv  = (const float*)d_in[6];
    const float* b_qkv  = (const float*)d_in[7];
    const float* w_o    = (const float*)d_in[8];
    const float* b_o    = (const float*)d_in[9];
    const float* w_fc1  = (const float*)d_in[10];
    const float* b_fc1  = (const float*)d_in[11];
    const float* w_fc2  = (const float*)d_in[12];
    const float* b_fc2  = (const float*)d_in[13];
    float* out = (float*)d_out;

    __half *xn, *qkvb, *attnb, *fc1b, *wc;
    float *x2;
    cudaGetSymbolAddress((void**)&xn,    g_xn);
    cudaGetSymbolAddress((void**)&qkvb,  g_qkv);
    cudaGetSymbolAddress((void**)&attnb, g_attn);
    cudaGetSymbolAddress((void**)&x2,    g_x2);
    cudaGetSymbolAddress((void**)&fc1b,  g_fc1);
    cudaGetSymbolAddress((void**)&wc,    g_wc);

    __half* wc_qkv = wc;
    __half* wc_o   = wc + (size_t)3 * M1;
    __half* wc_fc1 = wc + (size_t)4 * M1;
    __half* wc_fc2 = wc + (size_t)8 * M1;

    cudaFuncSetAttribute(gemm_mma<0>, cudaFuncAttributeMaxDynamicSharedMemorySize, GEMM_SMEM);
    cudaFuncSetAttribute(gemm_mma<1>, cudaFuncAttributeMaxDynamicSharedMemorySize, GEMM_SMEM);
    cudaFuncSetAttribute(gemm_mma<2>, cudaFuncAttributeMaxDynamicSharedMemorySize, GEMM_SMEM);
    cudaFuncSetAttribute(attn_tc, cudaFuncAttributeMaxDynamicSharedMemorySize, ATT_SMEM);

    // 0. Convert all weights to fp16, one launch (12M elements / 8 per thread)
    cvt_all_kernel<<<12 * M1 / 8 / 256, 256>>>(w_qkv, w_o, w_fc1, w_fc2, wc);

    // 1. LN1 -> fp16
    ln_kernel<<<MM, 256>>>(x, ln1_g, ln1_b, xn);
    // 2. QKV projection -> fp16
    gemm_mma<0><<<dim3(E3 / BN, MM / BM), 256, GEMM_SMEM>>>(xn, wc_qkv, b_qkv, nullptr,
                                                            qkvb, MM, E3, EE);
    // 3. FP16 tensor-core attention (double-buffered KV) -> fp16
    attn_tc<<<dim3(SS / 128, BB * HH), 256, ATT_SMEM>>>(qkvb, td, attnb);
    // 4. O projection + residual -> fp32
    gemm_mma<1><<<dim3(EE / BN, MM / BM), 256, GEMM_SMEM>>>(attnb, wc_o, b_o, x,
                                                            x2, MM, EE, EE);
    // 5. LN2 -> fp16
    ln_kernel<<<MM, 256>>>(x2, ln2_g, ln2_b, xn);
    // 6. FC1 + GELU -> fp16
    gemm_mma<2><<<dim3(FFD / BN, MM / BM), 256, GEMM_SMEM>>>(xn, wc_fc1, b_fc1, nullptr,
                                                             fc1b, MM, FFD, EE);
    // 7. FC2 + residual -> fp32 out
    gemm_mma<1><<<dim3(EE / BN, MM / BM), 256, GEMM_SMEM>>>(fc1b, wc_fc2, b_fc2, x2,
                                                            out, MM, EE, FFD);
}

// round 13
// speedup vs baseline: 2.1927x; 1.0607x over previous
#include <cuda_runtime.h>
#include <cuda_fp16.h>
#include <math.h>
#include <stdint.h>

// Problem constants
#define BB 4
#define SS 2048
#define EE 1024
#define HH 16
#define DH 64
#define FFD 4096
#define MM (BB * SS)          // 8192 tokens
#define E3 (3 * EE)           // 3072

// ---------------------------------------------------------------------------
// Scratch buffers (device globals; allocation-free)
// ---------------------------------------------------------------------------
__device__ __align__(128) __half g_xn[(size_t)MM * EE];     // LN out (fp16)
__device__ __align__(128) __half g_qkv[(size_t)MM * E3];    // QKV (fp16)
__device__ __align__(128) __half g_attn[(size_t)MM * EE];   // attention out (fp16)
__device__ __align__(128) float  g_x2[(size_t)MM * EE];     // residual (fp32)
__device__ __align__(128) __half g_fc1[(size_t)MM * FFD];   // gelu(fc1) (fp16)
// fp16 weights: qkv(3M) | o(1M) | fc1(4M) | fc2(4M)
__device__ __align__(128) __half g_wc[(size_t)12 * 1024 * 1024];

// ---------------------------------------------------------------------------
// Helpers
// ---------------------------------------------------------------------------
__device__ __forceinline__ uint32_t smem_u32(const void* p) {
    uint32_t a;
    asm("{ .reg .u64 t; cvta.to.shared.u64 t, %1; cvt.u32.u64 %0, t; }"
        : "=r"(a) : "l"(p));
    return a;
}
__device__ __forceinline__ void cp16(uint32_t s, const void* g) {
    asm volatile("cp.async.cg.shared.global [%0], [%1], 16;" :: "r"(s), "l"(g));
}
#define CP_COMMIT asm volatile("cp.async.commit_group;" ::: "memory")
#define CP_WAIT1  asm volatile("cp.async.wait_group 1;" ::: "memory")
#define CP_WAIT0  asm volatile("cp.async.wait_group 0;" ::: "memory")

// fp16 mma m16n8k16, fp32 accumulate
__device__ __forceinline__ void mmah(float c[4], const uint32_t a[4],
                                     uint32_t b0, uint32_t b1) {
    asm volatile(
        "mma.sync.aligned.m16n8k16.row.col.f32.f16.f16.f32 "
        "{%0,%1,%2,%3}, {%4,%5,%6,%7}, {%8,%9}, {%0,%1,%2,%3};"
        : "+f"(c[0]), "+f"(c[1]), "+f"(c[2]), "+f"(c[3])
        : "r"(a[0]), "r"(a[1]), "r"(a[2]), "r"(a[3]), "r"(b0), "r"(b1));
}
#define LDSM4(r, addr) \
    asm volatile("ldmatrix.sync.aligned.m8n8.x4.shared.b16 {%0,%1,%2,%3}, [%4];" \
        : "=r"((r)[0]), "=r"((r)[1]), "=r"((r)[2]), "=r"((r)[3]) : "r"(addr))
#define LDSM4T(r, addr) \
    asm volatile("ldmatrix.sync.aligned.m8n8.x4.trans.shared.b16 {%0,%1,%2,%3}, [%4];" \
        : "=r"((r)[0]), "=r"((r)[1]), "=r"((r)[2]), "=r"((r)[3]) : "r"(addr))

// ---------------------------------------------------------------------------
// Fused weight convert fp32 -> fp16 (all 4 weight matrices, one launch)
// ---------------------------------------------------------------------------
#define M1 (1024 * 1024)
__global__ void __launch_bounds__(256) cvt_all_kernel(
    const float* __restrict__ w_qkv, const float* __restrict__ w_o,
    const float* __restrict__ w_fc1, const float* __restrict__ w_fc2,
    __half* __restrict__ out) {
    int i = (blockIdx.x * 256 + threadIdx.x) * 8;   // [0, 12M)
    const float* src;
    int ofs;
    if (i < 3 * M1)       { src = w_qkv; ofs = i; }
    else if (i < 4 * M1)  { src = w_o;   ofs = i - 3 * M1; }
    else if (i < 8 * M1)  { src = w_fc1; ofs = i - 4 * M1; }
    else                  { src = w_fc2; ofs = i - 8 * M1; }
    float4 v0 = *(const float4*)(src + ofs);
    float4 v1 = *(const float4*)(src + ofs + 4);
    __half2 h[4];
    h[0] = __floats2half2_rn(v0.x, v0.y);
    h[1] = __floats2half2_rn(v0.z, v0.w);
    h[2] = __floats2half2_rn(v1.x, v1.y);
    h[3] = __floats2half2_rn(v1.z, v1.w);
    *(uint2*)(out + i)     = make_uint2(*(uint32_t*)&h[0], *(uint32_t*)&h[1]);
    *(uint2*)(out + i + 4) = make_uint2(*(uint32_t*)&h[2], *(uint32_t*)&h[3]);
}

// ---------------------------------------------------------------------------
// FP16 mma.sync GEMM NT (unchanged, proven)
// ---------------------------------------------------------------------------
#define BM 128
#define BN 128
#define BK 64
#define SROWB 144
#define ASTGB (BM * SROWB)
#define STGB (2 * ASTGB)
#define NSTG 3
#define GEMM_SMEM (NSTG * STGB)

template <int EPI>
__global__ void __launch_bounds__(256, 2) gemm_mma(
    const __half* __restrict__ A, const __half* __restrict__ W,
    const float* __restrict__ bias, const float* __restrict__ res,
    void* __restrict__ Cv, int M, int N, int K)
{
    extern __shared__ char smemraw[];
    const int tid = threadIdx.x;
    const int bm = blockIdx.y * BM;
    const int bn = blockIdx.x * BN;
    const uint32_t sbase = smem_u32(smemraw);

    const int w = tid >> 5, lane = tid & 31;
    const int t = lane & 3;
    const int g = lane >> 2;
    const int wm = (w & 3) * 32;
    const int wn = (w >> 2) * 64;

    const uint32_t aLd = (wm + (lane & 15)) * SROWB + ((lane >> 4) << 4);
    const uint32_t bLd = (wn + (lane & 7) + ((lane >> 4) << 3)) * SROWB
                         + (((lane >> 3) & 1) << 4);

    const __half* Ag = A + (size_t)bm * K;
    const __half* Wg = W + (size_t)bn * K;

    float acc[2][8][4];
    #pragma unroll
    for (int mi = 0; mi < 2; mi++)
        #pragma unroll
        for (int ni = 0; ni < 8; ni++)
            #pragma unroll
            for (int j = 0; j < 4; j++) acc[mi][ni][j] = 0.0f;

    auto load_tile = [&](int stg, int kt) {
        const uint32_t dA = sbase + stg * STGB;
        const uint32_t dB = dA + ASTGB;
        const int kofs = kt * BK;
        #pragma unroll
        for (int i = 0; i < 4; i++) {
            int chunk = tid + i * 256;
            int r = chunk >> 3, c = chunk & 7;
            cp16(dA + r * SROWB + c * 16, Ag + (size_t)r * K + kofs + c * 8);
        }
        #pragma unroll
        for (int i = 0; i < 4; i++) {
            int chunk = tid + i * 256;
            int r = chunk >> 3, c = chunk & 7;
            cp16(dB + r * SROWB + c * 16, Wg + (size_t)r * K + kofs + c * 8);
        }
    };

    const int nk = K / BK;
    load_tile(0, 0); CP_COMMIT;
    load_tile(1, 1); CP_COMMIT;

    for (int kt = 0; kt < nk; kt++) {
        const int s = kt % NSTG;
        CP_WAIT1;
        __syncthreads();
        const int nxt = kt + 2;
        if (nxt < nk) load_tile(nxt % NSTG, nxt);
        CP_COMMIT;

        const uint32_t aBase = sbase + s * STGB + aLd;
        const uint32_t bBase = sbase + s * STGB + ASTGB + bLd;

        #pragma unroll
        for (int ks = 0; ks < 4; ks++) {
            const uint32_t ko = ks * 32;
            uint32_t a0[4], a1[4], bq[4][4];
            LDSM4(a0, aBase + ko);
            LDSM4(a1, aBase + 16 * SROWB + ko);
            #pragma unroll
            for (int p = 0; p < 4; p++)
                LDSM4(bq[p], bBase + p * 16 * SROWB + ko);
            #pragma unroll
            for (int p = 0; p < 4; p++) {
                mmah(acc[0][2 * p],     a0, bq[p][0], bq[p][1]);
                mmah(acc[0][2 * p + 1], a0, bq[p][2], bq[p][3]);
                mmah(acc[1][2 * p],     a1, bq[p][0], bq[p][1]);
                mmah(acc[1][2 * p + 1], a1, bq[p][2], bq[p][3]);
            }
        }
    }

    float bb[8][2];
    #pragma unroll
    for (int ni = 0; ni < 8; ni++) {
        int col = bn + wn + ni * 8 + t * 2;
        bb[ni][0] = __ldg(bias + col);
        bb[ni][1] = __ldg(bias + col + 1);
    }
    #pragma unroll
    for (int mi = 0; mi < 2; mi++) {
        #pragma unroll
        for (int h = 0; h < 2; h++) {
            const int row = bm + wm + mi * 16 + g + h * 8;
            #pragma unroll
            for (int ni = 0; ni < 8; ni++) {
                const int col = bn + wn + ni * 8 + t * 2;
                float o0 = acc[mi][ni][h * 2 + 0] + bb[ni][0];
                float o1 = acc[mi][ni][h * 2 + 1] + bb[ni][1];
                if (EPI == 0) {
                    *(__half2*)((__half*)Cv + (size_t)row * N + col) =
                        __floats2half2_rn(o0, o1);
                } else if (EPI == 1) {
                    const float2 rv = *(const float2*)(res + (size_t)row * N + col);
                    *(float2*)((float*)Cv + (size_t)row * N + col) =
                        make_float2(o0 + rv.x, o1 + rv.y);
                } else {
                    o0 = 0.5f * o0 * (1.0f + erff(o0 * 0.70710678118654752f));
                    o1 = 0.5f * o1 * (1.0f + erff(o1 * 0.70710678118654752f));
                    *(__half2*)((__half*)Cv + (size_t)row * N + col) =
                        __floats2half2_rn(o0, o1);
                }
            }
        }
    }
}

// ---------------------------------------------------------------------------
// LayerNorm: one block per token row of 1024; fp16 output
// ---------------------------------------------------------------------------
__global__ void __launch_bounds__(256) ln_kernel(const float* __restrict__ x,
                                                 const float* __restrict__ g,
                                                 const float* __restrict__ b,
                                                 __half* __restrict__ out) {
    int row = blockIdx.x;
    const float4* xr = (const float4*)(x + (size_t)row * EE);
    float4 v = xr[threadIdx.x];
    float s  = v.x + v.y + v.z + v.w;
    float sq = v.x * v.x + v.y * v.y + v.z * v.z + v.w * v.w;
    #pragma unroll
    for (int o = 16; o; o >>= 1) {
        s  += __shfl_xor_sync(0xffffffffu, s,  o);
        sq += __shfl_xor_sync(0xffffffffu, sq, o);
    }
    __shared__ float ss[8], ssq[8];
    int w = threadIdx.x >> 5, ln = threadIdx.x & 31;
    if (ln == 0) { ss[w] = s; ssq[w] = sq; }
    __syncthreads();
    if (w == 0) {
        s  = (ln < 8) ? ss[ln]  : 0.0f;
        sq = (ln < 8) ? ssq[ln] : 0.0f;
        #pragma unroll
        for (int o = 4; o; o >>= 1) {
            s  += __shfl_xor_sync(0xffffffffu, s,  o);
            sq += __shfl_xor_sync(0xffffffffu, sq, o);
        }
        if (ln == 0) { ss[0] = s; ssq[0] = sq; }
    }
    __syncthreads();
    float mean = ss[0] * (1.0f / EE);
    float var  = ssq[0] * (1.0f / EE) - mean * mean;
    float rstd = rsqrtf(var + 1e-5f);
    int c = threadIdx.x * 4;
    float4 gg = *(const float4*)(g + c);
    float4 bb = *(const float4*)(b + c);
    __half2 h0 = __floats2half2_rn((v.x - mean) * rstd * gg.x + bb.x,
                                   (v.y - mean) * rstd * gg.y + bb.y);
    __half2 h1 = __floats2half2_rn((v.z - mean) * rstd * gg.z + bb.z,
                                   (v.w - mean) * rstd * gg.w + bb.w);
    *(uint2*)(out + (size_t)row * EE + c) =
        make_uint2(*(uint32_t*)&h0, *(uint32_t*)&h1);
}

// ---------------------------------------------------------------------------
// FP16 tensor-core flash attention, mask (j > i) || (j % TD == TD-1).
// Periodic mask via per-chunk smem LUT (no in-loop modulo); causal compare
// only on the two diagonal chunks. Double-buffered cp.async K/V.
// ---------------------------------------------------------------------------
#define AS2 72                          // smem row stride (halves) = 144 B
#define ASB (AS2 * 2)
#define KVB (128 * ASB)                 // one KV buffer (K 64 rows + V 64 rows)
#define ATT_SMEM ((128 + 256 + 128) * ASB + 256)

__global__ void __launch_bounds__(256, 2) attn_tc(const __half* __restrict__ qkv,
                                                  const int* __restrict__ tdp,
                                                  __half* __restrict__ out) {
    extern __shared__ char smemraw[];
    __half* Qs  = (__half*)smemraw;           // [128][AS2]
    __half* KV0 = Qs + 128 * AS2;             // 2 bufs x (K[64] + V[64])
    __half* Ps  = KV0 + 2 * 128 * AS2;        // [128][AS2]
    __half* kmaskS = Ps + 128 * AS2;          // [2][64] periodic-mask LUT

    const int qb = blockIdx.x, bh = blockIdx.y;
    const int b = bh >> 4, h = bh & 15;
    const int TD = tdp[0];
    const int tid = threadIdx.x, w = tid >> 5, lane = tid & 31;
    const int g = lane >> 2, t = lane & 3;

    const size_t base = (size_t)b * SS * E3 + (size_t)h * DH;
    const uint32_t kvBase = smem_u32(KV0);

    const uint32_t qLd = smem_u32(Qs) +
        (w * 16 + (lane & 15)) * ASB + ((lane >> 4) << 4);
    const uint32_t kLd0 = kvBase +
        ((lane & 7) + ((lane >> 4) << 3)) * ASB + (((lane >> 3) & 1) << 4);
    const uint32_t vLd0 = kvBase + 64 * ASB +
        (lane & 15) * ASB + ((lane >> 4) << 4);
    const uint32_t pLd = smem_u32(Ps) +
        (w * 16 + (lane & 15)) * ASB + ((lane >> 4) << 4);

    // load Q tile 128x64 halves
    for (int i = tid; i < 128 * 8; i += 256) {
        int r = i >> 3, c = (i & 7) * 8;
        *(uint4*)(Qs + r * AS2 + c) =
            *(const uint4*)(qkv + base + (size_t)(qb * 128 + r) * E3 + c);
    }

    auto load_kv = [&](int kb, int buf) {
        const uint32_t dst = kvBase + buf * KVB;
        #pragma unroll
        for (int i = 0; i < 2; i++) {
            int chunk = tid + i * 256;
            int r = chunk >> 3, cB = (chunk & 7) << 4;
            size_t off = base + (size_t)(kb * 64 + r) * E3 + (cB >> 1);
            cp16(dst + r * ASB + cB,            qkv + off + EE);
            cp16(dst + 64 * ASB + r * ASB + cB, qkv + off + 2 * EE);
        }
        if (tid < 64) {
            int col = kb * 64 + tid;
            kmaskS[buf * 64 + tid] =
                ((col % TD) == TD - 1) ? __float2half(0.0f) : __float2half(1.0f);
        }
    };

    float m0 = -1e30f, m1 = -1e30f, l0 = 0.0f, l1 = 0.0f;
    float o[8][4];
    #pragma unroll
    for (int ni = 0; ni < 8; ni++)
        #pragma unroll
        for (int j = 0; j < 4; j++) o[ni][j] = 0.0f;

    const int ig0 = qb * 128 + w * 16 + g;
    const int ig1 = ig0 + 8;
    const int nkt = 2 * qb + 2;

    load_kv(0, 0); CP_COMMIT;

    for (int kb = 0; kb < nkt; kb++) {
        const int buf = kb & 1;
        CP_WAIT0;
        __syncthreads();
        if (kb + 1 < nkt) load_kv(kb + 1, buf ^ 1);
        CP_COMMIT;

        const uint32_t kLd = kLd0 + buf * KVB;
        const uint32_t vLd = vLd0 + buf * KVB;

        // --- scores = Q @ K^T ---
        float s[8][4];
        #pragma unroll
        for (int ni = 0; ni < 8; ni++)
            #pragma unroll
            for (int j = 0; j < 4; j++) s[ni][j] = 0.0f;

        #pragma unroll
        for (int ks = 0; ks < 4; ks++) {
            const uint32_t ko = ks * 32;
            uint32_t aq[4];
            LDSM4(aq, qLd + ko);
            #pragma unroll
            for (int p = 0; p < 4; p++) {
                uint32_t bk[4];
                LDSM4(bk, kLd + p * 16 * ASB + ko);
                mmah(s[2 * p],     aq, bk[0], bk[1]);
                mmah(s[2 * p + 1], aq, bk[2], bk[3]);
            }
        }

        // --- scale (+ causal mask only on diagonal chunks) ---
        if (kb >= nkt - 2) {
            const int colb = kb * 64 + t * 2;
            #pragma unroll
            for (int ni = 0; ni < 8; ni++) {
                #pragma unroll
                for (int j = 0; j < 2; j++) {
                    const int col = colb + ni * 8 + j;
                    s[ni][j]     = (col > ig0) ? -1e30f : s[ni][j] * 0.125f;
                    s[ni][2 + j] = (col > ig1) ? -1e30f : s[ni][2 + j] * 0.125f;
                }
            }
        } else {
            #pragma unroll
            for (int ni = 0; ni < 8; ni++)
                #pragma unroll
                for (int j = 0; j < 4; j++) s[ni][j] *= 0.125f;
        }

        // --- online softmax (periodic mask applied post-exp via LUT) ---
        float rm0 = -1e30f, rm1 = -1e30f;
        #pragma unroll
        for (int ni = 0; ni < 8; ni++) {
            rm0 = fmaxf(rm0, fmaxf(s[ni][0], s[ni][1]));
            rm1 = fmaxf(rm1, fmaxf(s[ni][2], s[ni][3]));
        }
        #pragma unroll
        for (int ofs = 1; ofs < 4; ofs <<= 1) {
            rm0 = fmaxf(rm0, __shfl_xor_sync(0xffffffffu, rm0, ofs));
            rm1 = fmaxf(rm1, __shfl_xor_sync(0xffffffffu, rm1, ofs));
        }
        const float nm0 = fmaxf(m0, rm0), nm1 = fmaxf(m1, rm1);
        const float a0 = __expf(m0 - nm0), a1 = __expf(m1 - nm1);
        m0 = nm0; m1 = nm1;

        const __half2* km = (const __half2*)(kmaskS + buf * 64) + t;
        float rs0 = 0.0f, rs1 = 0.0f;
        __half* pR0 = Ps + (w * 16 + g) * AS2;
        __half* pR1 = pR0 + 8 * AS2;
        #pragma unroll
        for (int ni = 0; ni < 8; ni++) {
            const float2 mk = __half22float2(km[ni * 4]);
            float p00 = __expf(s[ni][0] - m0) * mk.x;
            float p01 = __expf(s[ni][1] - m0) * mk.y;
            float p10 = __expf(s[ni][2] - m1) * mk.x;
            float p11 = __expf(s[ni][3] - m1) * mk.y;
            rs0 += p00 + p01; rs1 += p10 + p11;
            const int c = ni * 8 + t * 2;
            *(__half2*)(pR0 + c) = __floats2half2_rn(p00, p01);
            *(__half2*)(pR1 + c) = __floats2half2_rn(p10, p11);
        }
        #pragma unroll
        for (int ofs = 1; ofs < 4; ofs <<= 1) {
            rs0 += __shfl_xor_sync(0xffffffffu, rs0, ofs);
            rs1 += __shfl_xor_sync(0xffffffffu, rs1, ofs);
        }
        l0 = l0 * a0 + rs0;
        l1 = l1 * a1 + rs1;
        #pragma unroll
        for (int ni = 0; ni < 8; ni++) {
            o[ni][0] *= a0; o[ni][1] *= a0;
            o[ni][2] *= a1; o[ni][3] *= a1;
        }
        __syncwarp();

        // --- O += P @ V (V B-fragment via ldmatrix.trans) ---
        #pragma unroll
        for (int ks = 0; ks < 4; ks++) {
            const uint32_t ko = ks * 32;
            uint32_t a[4];
            LDSM4(a, pLd + ko);
            const uint32_t vBase = vLd + ks * 16 * ASB;
            #pragma unroll
            for (int db = 0; db < 4; db++) {
                uint32_t bv[4];
                LDSM4T(bv, vBase + db * 32);
                mmah(o[2 * db],     a, bv[0], bv[1]);
                mmah(o[2 * db + 1], a, bv[2], bv[3]);
            }
        }
    }

    // epilogue -> fp16
    const float inv0 = 1.0f / l0, inv1 = 1.0f / l1;
    const size_t r0o = ((size_t)(b * SS + qb * 128 + w * 16 + g)) * EE + h * DH;
    const size_t r1o = r0o + 8 * EE;
    #pragma unroll
    for (int ni = 0; ni < 8; ni++) {
        const int c = ni * 8 + t * 2;
        *(__half2*)(out + r0o + c) = __floats2half2_rn(o[ni][0] * inv0, o[ni][1] * inv0);
        *(__half2*)(out + r1o + c) = __floats2half2_rn(o[ni][2] * inv1, o[ni][3] * inv1);
    }
}

// ---------------------------------------------------------------------------
// Launch
// ---------------------------------------------------------------------------
extern "C" void kernel_launch(void* const* d_in, const int* in_sizes, int n_in,
                              void* d_out, int out_size) {
    const float* x      = (const float*)d_in[0];
    const int*   td     = (const int*)d_in[1];
    const float* ln1_g  = (const float*)d_in[2];
    const float* ln1_b  = (const float*)d_in[3];
    const float* ln2_g  = (const float*)d_in[4];
    const float* ln2_b  = (const float*)d_in[5];
    const float* w_qkv  = (const float*)d_in[6];
    const float* b_qkv  = (const float*)d_in[7];
    const float* w_o    = (const float*)d_in[8];
    const float* b_o    = (const float*)d_in[9];
    const float* w_fc1  = (const float*)d_in[10];
    const float* b_fc1  = (const float*)d_in[11];
    const float* w_fc2  = (const float*)d_in[12];
    const float* b_fc2  = (const float*)d_in[13];
    float* out = (float*)d_out;

    __half *xn, *qkvb, *attnb, *fc1b, *wc;
    float *x2;
    cudaGetSymbolAddress((void**)&xn,    g_xn);
    cudaGetSymbolAddress((void**)&qkvb,  g_qkv);
    cudaGetSymbolAddress((void**)&attnb, g_attn);
    cudaGetSymbolAddress((void**)&x2,    g_x2);
    cudaGetSymbolAddress((void**)&fc1b,  g_fc1);
    cudaGetSymbolAddress((void**)&wc,    g_wc);

    __half* wc_qkv = wc;
    __half* wc_o   = wc + (size_t)3 * M1;
    __half* wc_fc1 = wc + (size_t)4 * M1;
    __half* wc_fc2 = wc + (size_t)8 * M1;

    cudaFuncSetAttribute(gemm_mma<0>, cudaFuncAttributeMaxDynamicSharedMemorySize, GEMM_SMEM);
    cudaFuncSetAttribute(gemm_mma<1>, cudaFuncAttributeMaxDynamicSharedMemorySize, GEMM_SMEM);
    cudaFuncSetAttribute(gemm_mma<2>, cudaFuncAttributeMaxDynamicSharedMemorySize, GEMM_SMEM);
    cudaFuncSetAttribute(attn_tc, cudaFuncAttributeMaxDynamicSharedMemorySize, ATT_SMEM);

    // 0. Convert all weights to fp16, one launch
    cvt_all_kernel<<<12 * M1 / 8 / 256, 256>>>(w_qkv, w_o, w_fc1, w_fc2, wc);

    // 1. LN1 -> fp16
    ln_kernel<<<MM, 256>>>(x, ln1_g, ln1_b, xn);
    // 2. QKV projection -> fp16
    gemm_mma<0><<<dim3(E3 / BN, MM / BM), 256, GEMM_SMEM>>>(xn, wc_qkv, b_qkv, nullptr,
                                                            qkvb, MM, E3, EE);
    // 3. FP16 tensor-core attention -> fp16
    attn_tc<<<dim3(SS / 128, BB * HH), 256, ATT_SMEM>>>(qkvb, td, attnb);
    // 4. O projection + residual -> fp32
    gemm_mma<1><<<dim3(EE / BN, MM / BM), 256, GEMM_SMEM>>>(attnb, wc_o, b_o, x,
                                                            x2, MM, EE, EE);
    // 5. LN2 -> fp16
    ln_kernel<<<MM, 256>>>(x2, ln2_g, ln2_b, xn);
    // 6. FC1 + GELU -> fp16
    gemm_mma<2><<<dim3(FFD / BN, MM / BM), 256, GEMM_SMEM>>>(xn, wc_fc1, b_fc1, nullptr,
                                                             fc1b, MM, FFD, EE);
    // 7. FC2 + residual -> fp32 out
    gemm_mma<1><<<dim3(EE / BN, MM / BM), 256, GEMM_SMEM>>>(fc1b, wc_fc2, b_fc2, x2,
                                                            out, MM, EE, FFD);
}

// round 14
// speedup vs baseline: 2.2362x; 1.0199x over previous
#include <cuda_runtime.h>
#include <cuda_fp16.h>
#include <math.h>
#include <stdint.h>

// Problem constants
#define BB 4
#define SS 2048
#define EE 1024
#define HH 16
#define DH 64
#define FFD 4096
#define MM (BB * SS)          // 8192 tokens
#define E3 (3 * EE)           // 3072

// ---------------------------------------------------------------------------
// Scratch buffers (device globals; allocation-free)
// ---------------------------------------------------------------------------
__device__ __align__(128) __half g_xn[(size_t)MM * EE];     // LN out (fp16)
__device__ __align__(128) __half g_qkv[(size_t)MM * E3];    // QKV (fp16)
__device__ __align__(128) __half g_attn[(size_t)MM * EE];   // attention out (fp16)
__device__ __align__(128) float  g_x2[(size_t)MM * EE];     // residual (fp32)
__device__ __align__(128) __half g_fc1[(size_t)MM * FFD];   // gelu(fc1) (fp16)
// fp16 weights: qkv(3M) | o(1M) | fc1(4M) | fc2(4M)
__device__ __align__(128) __half g_wc[(size_t)12 * 1024 * 1024];

// ---------------------------------------------------------------------------
// Helpers
// ---------------------------------------------------------------------------
__device__ __forceinline__ uint32_t smem_u32(const void* p) {
    uint32_t a;
    asm("{ .reg .u64 t; cvta.to.shared.u64 t, %1; cvt.u32.u64 %0, t; }"
        : "=r"(a) : "l"(p));
    return a;
}
__device__ __forceinline__ void cp16(uint32_t s, const void* g) {
    asm volatile("cp.async.cg.shared.global [%0], [%1], 16;" :: "r"(s), "l"(g));
}
#define CP_COMMIT asm volatile("cp.async.commit_group;" ::: "memory")
#define CP_WAIT1  asm volatile("cp.async.wait_group 1;" ::: "memory")
#define CP_WAIT0  asm volatile("cp.async.wait_group 0;" ::: "memory")

// fp16 mma m16n8k16, fp32 accumulate
__device__ __forceinline__ void mmah(float c[4], const uint32_t a[4],
                                     uint32_t b0, uint32_t b1) {
    asm volatile(
        "mma.sync.aligned.m16n8k16.row.col.f32.f16.f16.f32 "
        "{%0,%1,%2,%3}, {%4,%5,%6,%7}, {%8,%9}, {%0,%1,%2,%3};"
        : "+f"(c[0]), "+f"(c[1]), "+f"(c[2]), "+f"(c[3])
        : "r"(a[0]), "r"(a[1]), "r"(a[2]), "r"(a[3]), "r"(b0), "r"(b1));
}
#define LDSM4(r, addr) \
    asm volatile("ldmatrix.sync.aligned.m8n8.x4.shared.b16 {%0,%1,%2,%3}, [%4];" \
        : "=r"((r)[0]), "=r"((r)[1]), "=r"((r)[2]), "=r"((r)[3]) : "r"(addr))
#define LDSM4T(r, addr) \
    asm volatile("ldmatrix.sync.aligned.m8n8.x4.trans.shared.b16 {%0,%1,%2,%3}, [%4];" \
        : "=r"((r)[0]), "=r"((r)[1]), "=r"((r)[2]), "=r"((r)[3]) : "r"(addr))

__device__ __forceinline__ uint32_t packf2(float lo, float hi) {
    __half2 h = __floats2half2_rn(lo, hi);
    return *(uint32_t*)&h;
}

// ---------------------------------------------------------------------------
// Fused weight convert fp32 -> fp16 (all 4 weight matrices, one launch)
// ---------------------------------------------------------------------------
#define M1 (1024 * 1024)
__global__ void __launch_bounds__(256) cvt_all_kernel(
    const float* __restrict__ w_qkv, const float* __restrict__ w_o,
    const float* __restrict__ w_fc1, const float* __restrict__ w_fc2,
    __half* __restrict__ out) {
    int i = (blockIdx.x * 256 + threadIdx.x) * 8;   // [0, 12M)
    const float* src;
    int ofs;
    if (i < 3 * M1)       { src = w_qkv; ofs = i; }
    else if (i < 4 * M1)  { src = w_o;   ofs = i - 3 * M1; }
    else if (i < 8 * M1)  { src = w_fc1; ofs = i - 4 * M1; }
    else                  { src = w_fc2; ofs = i - 8 * M1; }
    float4 v0 = *(const float4*)(src + ofs);
    float4 v1 = *(const float4*)(src + ofs + 4);
    __half2 h[4];
    h[0] = __floats2half2_rn(v0.x, v0.y);
    h[1] = __floats2half2_rn(v0.z, v0.w);
    h[2] = __floats2half2_rn(v1.x, v1.y);
    h[3] = __floats2half2_rn(v1.z, v1.w);
    *(uint2*)(out + i)     = make_uint2(*(uint32_t*)&h[0], *(uint32_t*)&h[1]);
    *(uint2*)(out + i + 4) = make_uint2(*(uint32_t*)&h[2], *(uint32_t*)&h[3]);
}

// ---------------------------------------------------------------------------
// FP16 mma.sync GEMM NT (unchanged, proven)
// ---------------------------------------------------------------------------
#define BM 128
#define BN 128
#define BK 64
#define SROWB 144
#define ASTGB (BM * SROWB)
#define STGB (2 * ASTGB)
#define NSTG 3
#define GEMM_SMEM (NSTG * STGB)

template <int EPI>
__global__ void __launch_bounds__(256, 2) gemm_mma(
    const __half* __restrict__ A, const __half* __restrict__ W,
    const float* __restrict__ bias, const float* __restrict__ res,
    void* __restrict__ Cv, int M, int N, int K)
{
    extern __shared__ char smemraw[];
    const int tid = threadIdx.x;
    const int bm = blockIdx.y * BM;
    const int bn = blockIdx.x * BN;
    const uint32_t sbase = smem_u32(smemraw);

    const int w = tid >> 5, lane = tid & 31;
    const int t = lane & 3;
    const int g = lane >> 2;
    const int wm = (w & 3) * 32;
    const int wn = (w >> 2) * 64;

    const uint32_t aLd = (wm + (lane & 15)) * SROWB + ((lane >> 4) << 4);
    const uint32_t bLd = (wn + (lane & 7) + ((lane >> 4) << 3)) * SROWB
                         + (((lane >> 3) & 1) << 4);

    const __half* Ag = A + (size_t)bm * K;
    const __half* Wg = W + (size_t)bn * K;

    float acc[2][8][4];
    #pragma unroll
    for (int mi = 0; mi < 2; mi++)
        #pragma unroll
        for (int ni = 0; ni < 8; ni++)
            #pragma unroll
            for (int j = 0; j < 4; j++) acc[mi][ni][j] = 0.0f;

    auto load_tile = [&](int stg, int kt) {
        const uint32_t dA = sbase + stg * STGB;
        const uint32_t dB = dA + ASTGB;
        const int kofs = kt * BK;
        #pragma unroll
        for (int i = 0; i < 4; i++) {
            int chunk = tid + i * 256;
            int r = chunk >> 3, c = chunk & 7;
            cp16(dA + r * SROWB + c * 16, Ag + (size_t)r * K + kofs + c * 8);
        }
        #pragma unroll
        for (int i = 0; i < 4; i++) {
            int chunk = tid + i * 256;
            int r = chunk >> 3, c = chunk & 7;
            cp16(dB + r * SROWB + c * 16, Wg + (size_t)r * K + kofs + c * 8);
        }
    };

    const int nk = K / BK;
    load_tile(0, 0); CP_COMMIT;
    load_tile(1, 1); CP_COMMIT;

    for (int kt = 0; kt < nk; kt++) {
        const int s = kt % NSTG;
        CP_WAIT1;
        __syncthreads();
        const int nxt = kt + 2;
        if (nxt < nk) load_tile(nxt % NSTG, nxt);
        CP_COMMIT;

        const uint32_t aBase = sbase + s * STGB + aLd;
        const uint32_t bBase = sbase + s * STGB + ASTGB + bLd;

        #pragma unroll
        for (int ks = 0; ks < 4; ks++) {
            const uint32_t ko = ks * 32;
            uint32_t a0[4], a1[4], bq[4][4];
            LDSM4(a0, aBase + ko);
            LDSM4(a1, aBase + 16 * SROWB + ko);
            #pragma unroll
            for (int p = 0; p < 4; p++)
                LDSM4(bq[p], bBase + p * 16 * SROWB + ko);
            #pragma unroll
            for (int p = 0; p < 4; p++) {
                mmah(acc[0][2 * p],     a0, bq[p][0], bq[p][1]);
                mmah(acc[0][2 * p + 1], a0, bq[p][2], bq[p][3]);
                mmah(acc[1][2 * p],     a1, bq[p][0], bq[p][1]);
                mmah(acc[1][2 * p + 1], a1, bq[p][2], bq[p][3]);
            }
        }
    }

    float bb[8][2];
    #pragma unroll
    for (int ni = 0; ni < 8; ni++) {
        int col = bn + wn + ni * 8 + t * 2;
        bb[ni][0] = __ldg(bias + col);
        bb[ni][1] = __ldg(bias + col + 1);
    }
    #pragma unroll
    for (int mi = 0; mi < 2; mi++) {
        #pragma unroll
        for (int h = 0; h < 2; h++) {
            const int row = bm + wm + mi * 16 + g + h * 8;
            #pragma unroll
            for (int ni = 0; ni < 8; ni++) {
                const int col = bn + wn + ni * 8 + t * 2;
                float o0 = acc[mi][ni][h * 2 + 0] + bb[ni][0];
                float o1 = acc[mi][ni][h * 2 + 1] + bb[ni][1];
                if (EPI == 0) {
                    *(__half2*)((__half*)Cv + (size_t)row * N + col) =
                        __floats2half2_rn(o0, o1);
                } else if (EPI == 1) {
                    const float2 rv = *(const float2*)(res + (size_t)row * N + col);
                    *(float2*)((float*)Cv + (size_t)row * N + col) =
                        make_float2(o0 + rv.x, o1 + rv.y);
                } else {
                    o0 = 0.5f * o0 * (1.0f + erff(o0 * 0.70710678118654752f));
                    o1 = 0.5f * o1 * (1.0f + erff(o1 * 0.70710678118654752f));
                    *(__half2*)((__half*)Cv + (size_t)row * N + col) =
                        __floats2half2_rn(o0, o1);
                }
            }
        }
    }
}

// ---------------------------------------------------------------------------
// LayerNorm: one block per token row of 1024; fp16 output
// ---------------------------------------------------------------------------
__global__ void __launch_bounds__(256) ln_kernel(const float* __restrict__ x,
                                                 const float* __restrict__ g,
                                                 const float* __restrict__ b,
                                                 __half* __restrict__ out) {
    int row = blockIdx.x;
    const float4* xr = (const float4*)(x + (size_t)row * EE);
    float4 v = xr[threadIdx.x];
    float s  = v.x + v.y + v.z + v.w;
    float sq = v.x * v.x + v.y * v.y + v.z * v.z + v.w * v.w;
    #pragma unroll
    for (int o = 16; o; o >>= 1) {
        s  += __shfl_xor_sync(0xffffffffu, s,  o);
        sq += __shfl_xor_sync(0xffffffffu, sq, o);
    }
    __shared__ float ss[8], ssq[8];
    int w = threadIdx.x >> 5, ln = threadIdx.x & 31;
    if (ln == 0) { ss[w] = s; ssq[w] = sq; }
    __syncthreads();
    if (w == 0) {
        s  = (ln < 8) ? ss[ln]  : 0.0f;
        sq = (ln < 8) ? ssq[ln] : 0.0f;
        #pragma unroll
        for (int o = 4; o; o >>= 1) {
            s  += __shfl_xor_sync(0xffffffffu, s,  o);
            sq += __shfl_xor_sync(0xffffffffu, sq, o);
        }
        if (ln == 0) { ss[0] = s; ssq[0] = sq; }
    }
    __syncthreads();
    float mean = ss[0] * (1.0f / EE);
    float var  = ssq[0] * (1.0f / EE) - mean * mean;
    float rstd = rsqrtf(var + 1e-5f);
    int c = threadIdx.x * 4;
    float4 gg = *(const float4*)(g + c);
    float4 bb = *(const float4*)(b + c);
    __half2 h0 = __floats2half2_rn((v.x - mean) * rstd * gg.x + bb.x,
                                   (v.y - mean) * rstd * gg.y + bb.y);
    __half2 h1 = __floats2half2_rn((v.z - mean) * rstd * gg.z + bb.z,
                                   (v.w - mean) * rstd * gg.w + bb.w);
    *(uint2*)(out + (size_t)row * EE + c) =
        make_uint2(*(uint32_t*)&h0, *(uint32_t*)&h1);
}

// ---------------------------------------------------------------------------
// FP16 tensor-core flash attention, mask (j > i) || (j % TD == TD-1).
// Register-resident P (QK accumulator layout == PV A-fragment layout).
// Periodic mask via per-chunk smem LUT; causal compare on diagonal only.
// Double-buffered cp.async K/V.
// ---------------------------------------------------------------------------
#define AS2 72                          // smem row stride (halves) = 144 B
#define ASB (AS2 * 2)
#define KVB (128 * ASB)                 // one KV buffer (K 64 rows + V 64 rows)
#define ATT_SMEM ((128 + 256) * ASB + 256)

__global__ void __launch_bounds__(256, 2) attn_tc(const __half* __restrict__ qkv,
                                                  const int* __restrict__ tdp,
                                                  __half* __restrict__ out) {
    extern __shared__ char smemraw[];
    __half* Qs  = (__half*)smemraw;           // [128][AS2]
    __half* KV0 = Qs + 128 * AS2;             // 2 bufs x (K[64] + V[64])
    __half* kmaskS = KV0 + 2 * 128 * AS2;     // [2][64] periodic-mask LUT

    const int qb = blockIdx.x, bh = blockIdx.y;
    const int b = bh >> 4, h = bh & 15;
    const int TD = tdp[0];
    const int tid = threadIdx.x, w = tid >> 5, lane = tid & 31;
    const int g = lane >> 2, t = lane & 3;

    const size_t base = (size_t)b * SS * E3 + (size_t)h * DH;
    const uint32_t kvBase = smem_u32(KV0);

    const uint32_t qLd = smem_u32(Qs) +
        (w * 16 + (lane & 15)) * ASB + ((lane >> 4) << 4);
    const uint32_t kLd0 = kvBase +
        ((lane & 7) + ((lane >> 4) << 3)) * ASB + (((lane >> 3) & 1) << 4);
    const uint32_t vLd0 = kvBase + 64 * ASB +
        (lane & 15) * ASB + ((lane >> 4) << 4);

    // load Q tile 128x64 halves
    for (int i = tid; i < 128 * 8; i += 256) {
        int r = i >> 3, c = (i & 7) * 8;
        *(uint4*)(Qs + r * AS2 + c) =
            *(const uint4*)(qkv + base + (size_t)(qb * 128 + r) * E3 + c);
    }

    auto load_kv = [&](int kb, int buf) {
        const uint32_t dst = kvBase + buf * KVB;
        #pragma unroll
        for (int i = 0; i < 2; i++) {
            int chunk = tid + i * 256;
            int r = chunk >> 3, cB = (chunk & 7) << 4;
            size_t off = base + (size_t)(kb * 64 + r) * E3 + (cB >> 1);
            cp16(dst + r * ASB + cB,            qkv + off + EE);
            cp16(dst + 64 * ASB + r * ASB + cB, qkv + off + 2 * EE);
        }
        if (tid < 64) {
            int col = kb * 64 + tid;
            kmaskS[buf * 64 + tid] =
                ((col % TD) == TD - 1) ? __float2half(0.0f) : __float2half(1.0f);
        }
    };

    float m0 = -1e30f, m1 = -1e30f, l0 = 0.0f, l1 = 0.0f;
    float o[8][4];
    #pragma unroll
    for (int ni = 0; ni < 8; ni++)
        #pragma unroll
        for (int j = 0; j < 4; j++) o[ni][j] = 0.0f;

    const int ig0 = qb * 128 + w * 16 + g;
    const int ig1 = ig0 + 8;
    const int nkt = 2 * qb + 2;

    load_kv(0, 0); CP_COMMIT;

    for (int kb = 0; kb < nkt; kb++) {
        const int buf = kb & 1;
        CP_WAIT0;
        __syncthreads();
        if (kb + 1 < nkt) load_kv(kb + 1, buf ^ 1);
        CP_COMMIT;

        const uint32_t kLd = kLd0 + buf * KVB;
        const uint32_t vLd = vLd0 + buf * KVB;

        // --- scores = Q @ K^T ---
        float s[8][4];
        #pragma unroll
        for (int ni = 0; ni < 8; ni++)
            #pragma unroll
            for (int j = 0; j < 4; j++) s[ni][j] = 0.0f;

        #pragma unroll
        for (int ks = 0; ks < 4; ks++) {
            const uint32_t ko = ks * 32;
            uint32_t aq[4];
            LDSM4(aq, qLd + ko);
            #pragma unroll
            for (int p = 0; p < 4; p++) {
                uint32_t bk[4];
                LDSM4(bk, kLd + p * 16 * ASB + ko);
                mmah(s[2 * p],     aq, bk[0], bk[1]);
                mmah(s[2 * p + 1], aq, bk[2], bk[3]);
            }
        }

        // --- scale (+ causal mask only on diagonal chunks) ---
        if (kb >= nkt - 2) {
            const int colb = kb * 64 + t * 2;
            #pragma unroll
            for (int ni = 0; ni < 8; ni++) {
                #pragma unroll
                for (int j = 0; j < 2; j++) {
                    const int col = colb + ni * 8 + j;
                    s[ni][j]     = (col > ig0) ? -1e30f : s[ni][j] * 0.125f;
                    s[ni][2 + j] = (col > ig1) ? -1e30f : s[ni][2 + j] * 0.125f;
                }
            }
        } else {
            #pragma unroll
            for (int ni = 0; ni < 8; ni++)
                #pragma unroll
                for (int j = 0; j < 4; j++) s[ni][j] *= 0.125f;
        }

        // --- online softmax; P stays in registers (s -> probabilities) ---
        float rm0 = -1e30f, rm1 = -1e30f;
        #pragma unroll
        for (int ni = 0; ni < 8; ni++) {
            rm0 = fmaxf(rm0, fmaxf(s[ni][0], s[ni][1]));
            rm1 = fmaxf(rm1, fmaxf(s[ni][2], s[ni][3]));
        }
        #pragma unroll
        for (int ofs = 1; ofs < 4; ofs <<= 1) {
            rm0 = fmaxf(rm0, __shfl_xor_sync(0xffffffffu, rm0, ofs));
            rm1 = fmaxf(rm1, __shfl_xor_sync(0xffffffffu, rm1, ofs));
        }
        const float nm0 = fmaxf(m0, rm0), nm1 = fmaxf(m1, rm1);
        const float a0 = __expf(m0 - nm0), a1 = __expf(m1 - nm1);
        m0 = nm0; m1 = nm1;

        const __half2* km = (const __half2*)(kmaskS + buf * 64) + t;
        float rs0 = 0.0f, rs1 = 0.0f;
        #pragma unroll
        for (int ni = 0; ni < 8; ni++) {
            const float2 mk = __half22float2(km[ni * 4]);
            s[ni][0] = __expf(s[ni][0] - m0) * mk.x;
            s[ni][1] = __expf(s[ni][1] - m0) * mk.y;
            s[ni][2] = __expf(s[ni][2] - m1) * mk.x;
            s[ni][3] = __expf(s[ni][3] - m1) * mk.y;
            rs0 += s[ni][0] + s[ni][1];
            rs1 += s[ni][2] + s[ni][3];
        }
        #pragma unroll
        for (int ofs = 1; ofs < 4; ofs <<= 1) {
            rs0 += __shfl_xor_sync(0xffffffffu, rs0, ofs);
            rs1 += __shfl_xor_sync(0xffffffffu, rs1, ofs);
        }
        l0 = l0 * a0 + rs0;
        l1 = l1 * a1 + rs1;
        #pragma unroll
        for (int ni = 0; ni < 8; ni++) {
            o[ni][0] *= a0; o[ni][1] *= a0;
            o[ni][2] *= a1; o[ni][3] *= a1;
        }

        // --- O += P @ V (P A-fragment packed from registers; V via trans) ---
        #pragma unroll
        for (int ks = 0; ks < 4; ks++) {
            uint32_t a[4];
            a[0] = packf2(s[2 * ks][0],     s[2 * ks][1]);
            a[1] = packf2(s[2 * ks][2],     s[2 * ks][3]);
            a[2] = packf2(s[2 * ks + 1][0], s[2 * ks + 1][1]);
            a[3] = packf2(s[2 * ks + 1][2], s[2 * ks + 1][3]);
            const uint32_t vBase = vLd + ks * 16 * ASB;
            #pragma unroll
            for (int db = 0; db < 4; db++) {
                uint32_t bv[4];
                LDSM4T(bv, vBase + db * 32);
                mmah(o[2 * db],     a, bv[0], bv[1]);
                mmah(o[2 * db + 1], a, bv[2], bv[3]);
            }
        }
    }

    // epilogue -> fp16
    const float inv0 = 1.0f / l0, inv1 = 1.0f / l1;
    const size_t r0o = ((size_t)(b * SS + qb * 128 + w * 16 + g)) * EE + h * DH;
    const size_t r1o = r0o + 8 * EE;
    #pragma unroll
    for (int ni = 0; ni < 8; ni++) {
        const int c = ni * 8 + t * 2;
        *(__half2*)(out + r0o + c) = __floats2half2_rn(o[ni][0] * inv0, o[ni][1] * inv0);
        *(__half2*)(out + r1o + c) = __floats2half2_rn(o[ni][2] * inv1, o[ni][3] * inv1);
    }
}

// ---------------------------------------------------------------------------
// Launch
// ---------------------------------------------------------------------------
extern "C" void kernel_launch(void* const* d_in, const int* in_sizes, int n_in,
                              void* d_out, int out_size) {
    const float* x      = (const float*)d_in[0];
    const int*   td     = (const int*)d_in[1];
    const float* ln1_g  = (const float*)d_in[2];
    const float* ln1_b  = (const float*)d_in[3];
    const float* ln2_g  = (const float*)d_in[4];
    const float* ln2_b  = (const float*)d_in[5];
    const float* w_qkv  = (const float*)d_in[6];
    const float* b_qkv  = (const float*)d_in[7];
    const float* w_o    = (const float*)d_in[8];
    const float* b_o    = (const float*)d_in[9];
    const float* w_fc1  = (const float*)d_in[10];
    const float* b_fc1  = (const float*)d_in[11];
    const float* w_fc2  = (const float*)d_in[12];
    const float* b_fc2  = (const float*)d_in[13];
    float* out = (float*)d_out;

    __half *xn, *qkvb, *attnb, *fc1b, *wc;
    float *x2;
    cudaGetSymbolAddress((void**)&xn,    g_xn);
    cudaGetSymbolAddress((void**)&qkvb,  g_qkv);
    cudaGetSymbolAddress((void**)&attnb, g_attn);
    cudaGetSymbolAddress((void**)&x2,    g_x2);
    cudaGetSymbolAddress((void**)&fc1b,  g_fc1);
    cudaGetSymbolAddress((void**)&wc,    g_wc);

    __half* wc_qkv = wc;
    __half* wc_o   = wc + (size_t)3 * M1;
    __half* wc_fc1 = wc + (size_t)4 * M1;
    __half* wc_fc2 = wc + (size_t)8 * M1;

    cudaFuncSetAttribute(gemm_mma<0>, cudaFuncAttributeMaxDynamicSharedMemorySize, GEMM_SMEM);
    cudaFuncSetAttribute(gemm_mma<1>, cudaFuncAttributeMaxDynamicSharedMemorySize, GEMM_SMEM);
    cudaFuncSetAttribute(gemm_mma<2>, cudaFuncAttributeMaxDynamicSharedMemorySize, GEMM_SMEM);
    cudaFuncSetAttribute(attn_tc, cudaFuncAttributeMaxDynamicSharedMemorySize, ATT_SMEM);

    // 0. Convert all weights to fp16, one launch
    cvt_all_kernel<<<12 * M1 / 8 / 256, 256>>>(w_qkv, w_o, w_fc1, w_fc2, wc);

    // 1. LN1 -> fp16
    ln_kernel<<<MM, 256>>>(x, ln1_g, ln1_b, xn);
    // 2. QKV projection -> fp16
    gemm_mma<0><<<dim3(E3 / BN, MM / BM), 256, GEMM_SMEM>>>(xn, wc_qkv, b_qkv, nullptr,
                                                            qkvb, MM, E3, EE);
    // 3. FP16 tensor-core attention -> fp16
    attn_tc<<<dim3(SS / 128, BB * HH), 256, ATT_SMEM>>>(qkvb, td, attnb);
    // 4. O projection + residual -> fp32
    gemm_mma<1><<<dim3(EE / BN, MM / BM), 256, GEMM_SMEM>>>(attnb, wc_o, b_o, x,
                                                            x2, MM, EE, EE);
    // 5. LN2 -> fp16
    ln_kernel<<<MM, 256>>>(x2, ln2_g, ln2_b, xn);
    // 6. FC1 + GELU -> fp16
    gemm_mma<2><<<dim3(FFD / BN, MM / BM), 256, GEMM_SMEM>>>(xn, wc_fc1, b_fc1, nullptr,
                                                             fc1b, MM, FFD, EE);
    // 7. FC2 + residual -> fp32 out
    gemm_mma<1><<<dim3(EE / BN, MM / BM), 256, GEMM_SMEM>>>(fc1b, wc_fc2, b_fc2, x2,
                                                            out, MM, EE, FFD);
}